// round 1
// baseline (speedup 1.0000x reference)
#include <cuda_runtime.h>
#include <cuda_bf16.h>
#include <cstdint>
#include <cstdio>

// ---------------- problem constants ----------------
#define BIMG   16
#define HH     128
#define WW_    128
#define CC     192
#define HEADS  6
#define HD     32
#define WIN    8
#define SHIFT  4
#define NTOK   (BIMG * HH * WW_)          // 262144 tokens
#define NWIN   (BIMG * (HH/WIN) * (WW_/WIN))  // 4096 windows
#define NN     (WIN * WIN)                // 64 tokens per window

// ---------------- scratch (device globals; no allocation allowed) ----------------
__device__ float g_hwin [ (size_t)NTOK * CC ];        // LN1 + windowed input (reused for LN2 out)
__device__ float g_qkv  [ (size_t)NTOK * 3 * CC ];    // qkv in window order
__device__ float g_attno[ (size_t)NTOK * CC ];        // attention output (window order)
__device__ float g_projo[ (size_t)NTOK * CC ];        // proj output (window order)
__device__ float g_x1   [ (size_t)NTOK * CC ];        // residual-1 result (original order)
__device__ float g_mlp1 [ (size_t)NTOK * 4 * CC ];    // MLP hidden

// ---------------- LN1 + cyclic shift + window partition (warp per token) ----------------
__global__ __launch_bounds__(256) void ln1_gather_k(
    const float* __restrict__ x, const float* __restrict__ g,
    const float* __restrict__ beta, float* __restrict__ out)
{
    int warp = (blockIdx.x * blockDim.x + threadIdx.x) >> 5;
    int lane = threadIdx.x & 31;
    if (warp >= NTOK) return;
    int win = warp >> 6, n = warp & 63;
    int b   = win >> 8;
    int wh  = (win >> 4) & 15;
    int ww  = win & 15;
    int r   = n >> 3, c = n & 7;
    int i = (wh * WIN + r + SHIFT) & 127;
    int j = (ww * WIN + c + SHIFT) & 127;
    const float* src = x + ((size_t)b * (HH*WW_) + (size_t)i * WW_ + j) * CC;

    float v[6];
    float sum = 0.f;
    #pragma unroll
    for (int u = 0; u < 6; ++u) { v[u] = src[lane + u*32]; sum += v[u]; }
    #pragma unroll
    for (int o = 16; o; o >>= 1) sum += __shfl_xor_sync(0xffffffffu, sum, o);
    float mean = sum * (1.f/192.f);
    float var = 0.f;
    #pragma unroll
    for (int u = 0; u < 6; ++u) { float d = v[u]-mean; var += d*d; }
    #pragma unroll
    for (int o = 16; o; o >>= 1) var += __shfl_xor_sync(0xffffffffu, var, o);
    var *= (1.f/192.f);
    float rstd = rsqrtf(var + 1e-5f);
    float* dst = out + (size_t)warp * CC;
    #pragma unroll
    for (int u = 0; u < 6; ++u) {
        int ch = lane + u*32;
        dst[ch] = (v[u]-mean)*rstd*g[ch] + beta[ch];
    }
}

// ---------------- plain LN (warp per token) ----------------
__global__ __launch_bounds__(256) void ln2_k(
    const float* __restrict__ x, const float* __restrict__ g,
    const float* __restrict__ beta, float* __restrict__ out)
{
    int warp = (blockIdx.x * blockDim.x + threadIdx.x) >> 5;
    int lane = threadIdx.x & 31;
    if (warp >= NTOK) return;
    const float* src = x + (size_t)warp * CC;
    float v[6];
    float sum = 0.f;
    #pragma unroll
    for (int u = 0; u < 6; ++u) { v[u] = src[lane + u*32]; sum += v[u]; }
    #pragma unroll
    for (int o = 16; o; o >>= 1) sum += __shfl_xor_sync(0xffffffffu, sum, o);
    float mean = sum * (1.f/192.f);
    float var = 0.f;
    #pragma unroll
    for (int u = 0; u < 6; ++u) { float d = v[u]-mean; var += d*d; }
    #pragma unroll
    for (int o = 16; o; o >>= 1) var += __shfl_xor_sync(0xffffffffu, var, o);
    var *= (1.f/192.f);
    float rstd = rsqrtf(var + 1e-5f);
    float* dst = out + (size_t)warp * CC;
    #pragma unroll
    for (int u = 0; u < 6; ++u) {
        int ch = lane + u*32;
        dst[ch] = (v[u]-mean)*rstd*g[ch] + beta[ch];
    }
}

// ---------------- SGEMM: C[M,N] = A[M,K] @ B[N,K]^T + bias, epilogue variants ----------------
// EPI 0: +bias. EPI 1: +bias then exact GELU. EPI 2: +bias +resid (residual add).
template<int EPI>
__global__ __launch_bounds__(256) void sgemm_k(
    const float* __restrict__ A, const float* __restrict__ B,
    const float* __restrict__ bias, const float* __restrict__ resid,
    float* __restrict__ C, int M, int N, int K)
{
    __shared__ float As[16][64];
    __shared__ float Bs[16][64];
    const int bm = blockIdx.y * 64;
    const int bn = blockIdx.x * 64;
    const int tid = threadIdx.x;
    const int tx = tid & 15, ty = tid >> 4;
    const int lrow = tid >> 2;            // 0..63
    const int lcol = (tid & 3) << 2;      // 0,4,8,12
    const float* Ap = A + (size_t)(bm + lrow) * K + lcol;
    const float* Bp = B + (size_t)(bn + lrow) * K + lcol;

    float acc[4][4] = {};
    for (int k0 = 0; k0 < K; k0 += 16) {
        float4 av = *(const float4*)(Ap + k0);
        float4 bv = *(const float4*)(Bp + k0);
        As[lcol+0][lrow] = av.x; As[lcol+1][lrow] = av.y;
        As[lcol+2][lrow] = av.z; As[lcol+3][lrow] = av.w;
        Bs[lcol+0][lrow] = bv.x; Bs[lcol+1][lrow] = bv.y;
        Bs[lcol+2][lrow] = bv.z; Bs[lcol+3][lrow] = bv.w;
        __syncthreads();
        #pragma unroll
        for (int k = 0; k < 16; ++k) {
            float4 a4 = *(const float4*)&As[k][ty << 2];
            float4 b4 = *(const float4*)&Bs[k][tx << 2];
            float ar[4] = {a4.x, a4.y, a4.z, a4.w};
            float br[4] = {b4.x, b4.y, b4.z, b4.w};
            #pragma unroll
            for (int i = 0; i < 4; ++i)
                #pragma unroll
                for (int j = 0; j < 4; ++j)
                    acc[i][j] += ar[i] * br[j];
        }
        __syncthreads();
    }
    #pragma unroll
    for (int i = 0; i < 4; ++i) {
        int row = bm + (ty << 2) + i;
        #pragma unroll
        for (int j = 0; j < 4; ++j) {
            int col = bn + (tx << 2) + j;
            float v = acc[i][j] + bias[col];
            if (EPI == 1) v = 0.5f * v * (1.0f + erff(v * 0.70710678118654752f));
            if (EPI == 2) v += resid[(size_t)row * N + col];
            C[(size_t)row * N + col] = v;
        }
    }
}

// ---------------- windowed attention: one block per (window, head), 64 threads ----------------
__global__ __launch_bounds__(64) void attn_k(
    const float* __restrict__ qkv, float* __restrict__ attno)
{
    const int win = blockIdx.x / HEADS;
    const int h   = blockIdx.x % HEADS;
    const int t   = threadIdx.x;                // token row within window
    __shared__ float ks[NN][HD + 1];
    __shared__ float vs[NN][HD + 1];

    const float* base = qkv + (size_t)(win * NN + t) * (3*CC) + h * HD;

    float q[HD];
    float nq = 0.f;
    #pragma unroll
    for (int d = 0; d < HD; ++d) { q[d] = base[d]; nq += q[d]*q[d]; }
    nq = fmaxf(sqrtf(nq), 1e-12f);
    float invq = 1.f / nq;
    #pragma unroll
    for (int d = 0; d < HD; ++d) q[d] *= invq;

    float kr[HD];
    float nk = 0.f;
    #pragma unroll
    for (int d = 0; d < HD; ++d) { kr[d] = base[CC + d]; nk += kr[d]*kr[d]; }
    nk = fmaxf(sqrtf(nk), 1e-12f);
    float invk = 1.f / nk;
    #pragma unroll
    for (int d = 0; d < HD; ++d) ks[t][d] = kr[d] * invk;
    #pragma unroll
    for (int d = 0; d < HD; ++d) vs[t][d] = base[2*CC + d];
    __syncthreads();

    const float scale = 0.17677669529663687f;   // 1/sqrt(32)
    float s[NN];
    float mx = -1e30f;
    #pragma unroll 4
    for (int m = 0; m < NN; ++m) {
        float dot = 0.f;
        #pragma unroll
        for (int d = 0; d < HD; ++d) dot += q[d] * ks[m][d];
        s[m] = dot * scale;
        mx = fmaxf(mx, s[m]);
    }
    float sum = 0.f;
    #pragma unroll 4
    for (int m = 0; m < NN; ++m) { s[m] = expf(s[m] - mx); sum += s[m]; }
    float rs = 1.f / sum;
    float o[HD] = {};
    #pragma unroll 4
    for (int m = 0; m < NN; ++m) {
        float p = fminf(fmaxf(s[m] * rs, 1e-6f), 1.0f);
        #pragma unroll
        for (int d = 0; d < HD; ++d) o[d] += p * vs[m][d];
    }
    float* dst = attno + (size_t)(win * NN + t) * CC + h * HD;
    #pragma unroll
    for (int d = 0; d < HD; ++d) dst[d] = o[d];
}

// ---------------- window reverse + un-shift + residual add ----------------
__global__ __launch_bounds__(256) void rev_res_k(
    const float* __restrict__ x, const float* __restrict__ projo,
    float* __restrict__ x1)
{
    const size_t total = (size_t)NTOK * (CC/4);
    size_t idx = (size_t)blockIdx.x * blockDim.x + threadIdx.x;
    if (idx >= total) return;
    int t  = (int)(idx / (CC/4));
    int c4 = (int)(idx % (CC/4));
    int b   = t >> 14;
    int rem = t & 16383;
    int i = rem >> 7, j = rem & 127;
    int ip = (i + 128 - SHIFT) & 127;
    int jp = (j + 128 - SHIFT) & 127;
    int win = b * 256 + (ip >> 3) * 16 + (jp >> 3);
    int n   = ((ip & 7) << 3) + (jp & 7);
    float4 a = ((const float4*)x)[(size_t)t * (CC/4) + c4];
    float4 p = ((const float4*)projo)[(size_t)(win * NN + n) * (CC/4) + c4];
    float4 r;
    r.x = a.x + p.x; r.y = a.y + p.y; r.z = a.z + p.z; r.w = a.w + p.w;
    ((float4*)x1)[(size_t)t * (CC/4) + c4] = r;
}

// ---------------- host launcher ----------------
extern "C" void kernel_launch(void* const* d_in, const int* in_sizes, int n_in,
                              void* d_out, int out_size)
{
    const float* x      = (const float*)d_in[0];
    const float* qkv_w  = (const float*)d_in[1];
    const float* qkv_b  = (const float*)d_in[2];
    const float* proj_w = (const float*)d_in[3];
    const float* proj_b = (const float*)d_in[4];
    const float* n1_g   = (const float*)d_in[5];
    const float* n1_b   = (const float*)d_in[6];
    const float* n2_g   = (const float*)d_in[7];
    const float* n2_b   = (const float*)d_in[8];
    const float* w1     = (const float*)d_in[9];
    const float* b1     = (const float*)d_in[10];
    const float* w2     = (const float*)d_in[11];
    const float* b2     = (const float*)d_in[12];
    float* out = (float*)d_out;

    float *hwin, *qkv, *attno, *projo, *x1, *mlp1;
    cudaGetSymbolAddress((void**)&hwin,  g_hwin);
    cudaGetSymbolAddress((void**)&qkv,   g_qkv);
    cudaGetSymbolAddress((void**)&attno, g_attno);
    cudaGetSymbolAddress((void**)&projo, g_projo);
    cudaGetSymbolAddress((void**)&x1,    g_x1);
    cudaGetSymbolAddress((void**)&mlp1,  g_mlp1);

    // 1) LN1 + shift + window gather
    ln1_gather_k<<<NTOK/8, 256>>>(x, n1_g, n1_b, hwin);

    // 2) QKV GEMM: (262144,192) @ (576,192)^T
    sgemm_k<0><<<dim3((3*CC)/64, NTOK/64), 256>>>(hwin, qkv_w, qkv_b, nullptr, qkv,
                                                  NTOK, 3*CC, CC);

    // 3) attention per (window, head)
    attn_k<<<NWIN * HEADS, 64>>>(qkv, attno);

    // 4) proj GEMM
    sgemm_k<0><<<dim3(CC/64, NTOK/64), 256>>>(attno, proj_w, proj_b, nullptr, projo,
                                              NTOK, CC, CC);

    // 5) window reverse + un-shift + residual
    {
        size_t total = (size_t)NTOK * (CC/4);
        int blocks = (int)((total + 255) / 256);
        rev_res_k<<<blocks, 256>>>(x, projo, x1);
    }

    // 6) LN2 (reuse hwin buffer)
    ln2_k<<<NTOK/8, 256>>>(x1, n2_g, n2_b, hwin);

    // 7) MLP1 GEMM + GELU
    sgemm_k<1><<<dim3((4*CC)/64, NTOK/64), 256>>>(hwin, w1, b1, nullptr, mlp1,
                                                  NTOK, 4*CC, CC);

    // 8) MLP2 GEMM + bias + residual -> out
    sgemm_k<2><<<dim3(CC/64, NTOK/64), 256>>>(mlp1, w2, b2, x1, out,
                                              NTOK, CC, 4*CC);
}

// round 2
// speedup vs baseline: 1.0591x; 1.0591x over previous
#include <cuda_runtime.h>
#include <cuda_bf16.h>
#include <cstdint>
#include <cstdio>

// ---------------- problem constants ----------------
#define BIMG   16
#define HH     128
#define WW_    128
#define CC     192
#define HEADS  6
#define HD     32
#define WIN    8
#define SHIFT  4
#define NTOK   (BIMG * HH * WW_)          // 262144 tokens
#define NWIN   (BIMG * (HH/WIN) * (WW_/WIN))  // 4096 windows
#define NN     (WIN * WIN)                // 64 tokens per window

// ---------------- scratch (device globals; no allocation allowed) ----------------
__device__ float g_hwin [ (size_t)NTOK * CC ];        // LN1 + windowed input (reused for LN2 out)
__device__ float g_qkv  [ (size_t)NTOK * 3 * CC ];    // qkv in window order
__device__ float g_attno[ (size_t)NTOK * CC ];        // attention output (window order)
__device__ float g_projo[ (size_t)NTOK * CC ];        // proj output (window order)
__device__ float g_x1   [ (size_t)NTOK * CC ];        // residual-1 result (original order)
__device__ float g_mlp1 [ (size_t)NTOK * 4 * CC ];    // MLP hidden

// ---------------- LN1 + cyclic shift + window partition (warp per token) ----------------
__global__ __launch_bounds__(256) void ln1_gather_k(
    const float* __restrict__ x, const float* __restrict__ g,
    const float* __restrict__ beta, float* __restrict__ out)
{
    int warp = (blockIdx.x * blockDim.x + threadIdx.x) >> 5;
    int lane = threadIdx.x & 31;
    if (warp >= NTOK) return;
    int win = warp >> 6, n = warp & 63;
    int b   = win >> 8;
    int wh  = (win >> 4) & 15;
    int ww  = win & 15;
    int r   = n >> 3, c = n & 7;
    int i = (wh * WIN + r + SHIFT) & 127;
    int j = (ww * WIN + c + SHIFT) & 127;
    const float* src = x + ((size_t)b * (HH*WW_) + (size_t)i * WW_ + j) * CC;

    float v[6];
    float sum = 0.f;
    #pragma unroll
    for (int u = 0; u < 6; ++u) { v[u] = src[lane + u*32]; sum += v[u]; }
    #pragma unroll
    for (int o = 16; o; o >>= 1) sum += __shfl_xor_sync(0xffffffffu, sum, o);
    float mean = sum * (1.f/192.f);
    float var = 0.f;
    #pragma unroll
    for (int u = 0; u < 6; ++u) { float d = v[u]-mean; var += d*d; }
    #pragma unroll
    for (int o = 16; o; o >>= 1) var += __shfl_xor_sync(0xffffffffu, var, o);
    var *= (1.f/192.f);
    float rstd = rsqrtf(var + 1e-5f);
    float* dst = out + (size_t)warp * CC;
    #pragma unroll
    for (int u = 0; u < 6; ++u) {
        int ch = lane + u*32;
        dst[ch] = (v[u]-mean)*rstd*g[ch] + beta[ch];
    }
}

// ---------------- plain LN (warp per token) ----------------
__global__ __launch_bounds__(256) void ln2_k(
    const float* __restrict__ x, const float* __restrict__ g,
    const float* __restrict__ beta, float* __restrict__ out)
{
    int warp = (blockIdx.x * blockDim.x + threadIdx.x) >> 5;
    int lane = threadIdx.x & 31;
    if (warp >= NTOK) return;
    const float* src = x + (size_t)warp * CC;
    float v[6];
    float sum = 0.f;
    #pragma unroll
    for (int u = 0; u < 6; ++u) { v[u] = src[lane + u*32]; sum += v[u]; }
    #pragma unroll
    for (int o = 16; o; o >>= 1) sum += __shfl_xor_sync(0xffffffffu, sum, o);
    float mean = sum * (1.f/192.f);
    float var = 0.f;
    #pragma unroll
    for (int u = 0; u < 6; ++u) { float d = v[u]-mean; var += d*d; }
    #pragma unroll
    for (int o = 16; o; o >>= 1) var += __shfl_xor_sync(0xffffffffu, var, o);
    var *= (1.f/192.f);
    float rstd = rsqrtf(var + 1e-5f);
    float* dst = out + (size_t)warp * CC;
    #pragma unroll
    for (int u = 0; u < 6; ++u) {
        int ch = lane + u*32;
        dst[ch] = (v[u]-mean)*rstd*g[ch] + beta[ch];
    }
}

// ---------------- SGEMM: C[M,N] = A[M,K] @ B[N,K]^T + bias, epilogue variants ----------------
// EPI 0: +bias. EPI 1: +bias then exact GELU. EPI 2: +bias +resid (residual add).
template<int EPI>
__global__ __launch_bounds__(256) void sgemm_k(
    const float* __restrict__ A, const float* __restrict__ B,
    const float* __restrict__ bias, const float* __restrict__ resid,
    float* __restrict__ C, int M, int N, int K)
{
    __shared__ float As[16][64];
    __shared__ float Bs[16][64];
    const int bm = blockIdx.y * 64;
    const int bn = blockIdx.x * 64;
    const int tid = threadIdx.x;
    const int tx = tid & 15, ty = tid >> 4;
    const int lrow = tid >> 2;            // 0..63
    const int lcol = (tid & 3) << 2;      // 0,4,8,12
    const float* Ap = A + (size_t)(bm + lrow) * K + lcol;
    const float* Bp = B + (size_t)(bn + lrow) * K + lcol;

    float acc[4][4] = {};
    for (int k0 = 0; k0 < K; k0 += 16) {
        float4 av = *(const float4*)(Ap + k0);
        float4 bv = *(const float4*)(Bp + k0);
        As[lcol+0][lrow] = av.x; As[lcol+1][lrow] = av.y;
        As[lcol+2][lrow] = av.z; As[lcol+3][lrow] = av.w;
        Bs[lcol+0][lrow] = bv.x; Bs[lcol+1][lrow] = bv.y;
        Bs[lcol+2][lrow] = bv.z; Bs[lcol+3][lrow] = bv.w;
        __syncthreads();
        #pragma unroll
        for (int k = 0; k < 16; ++k) {
            float4 a4 = *(const float4*)&As[k][ty << 2];
            float4 b4 = *(const float4*)&Bs[k][tx << 2];
            float ar[4] = {a4.x, a4.y, a4.z, a4.w};
            float br[4] = {b4.x, b4.y, b4.z, b4.w};
            #pragma unroll
            for (int i = 0; i < 4; ++i)
                #pragma unroll
                for (int j = 0; j < 4; ++j)
                    acc[i][j] += ar[i] * br[j];
        }
        __syncthreads();
    }
    #pragma unroll
    for (int i = 0; i < 4; ++i) {
        int row = bm + (ty << 2) + i;
        #pragma unroll
        for (int j = 0; j < 4; ++j) {
            int col = bn + (tx << 2) + j;
            float v = acc[i][j] + bias[col];
            if (EPI == 1) v = 0.5f * v * (1.0f + erff(v * 0.70710678118654752f));
            if (EPI == 2) v += resid[(size_t)row * N + col];
            C[(size_t)row * N + col] = v;
        }
    }
}

// ---------------- windowed attention: one block per (window, head), 64 threads ----------------
__global__ __launch_bounds__(64) void attn_k(
    const float* __restrict__ qkv, float* __restrict__ attno)
{
    const int win = blockIdx.x / HEADS;
    const int h   = blockIdx.x % HEADS;
    const int t   = threadIdx.x;                // token row within window
    __shared__ float ks[NN][HD + 1];
    __shared__ float vs[NN][HD + 1];

    const float* base = qkv + (size_t)(win * NN + t) * (3*CC) + h * HD;

    float q[HD];
    float nq = 0.f;
    #pragma unroll
    for (int d = 0; d < HD; ++d) { q[d] = base[d]; nq += q[d]*q[d]; }
    nq = fmaxf(sqrtf(nq), 1e-12f);
    float invq = 1.f / nq;
    #pragma unroll
    for (int d = 0; d < HD; ++d) q[d] *= invq;

    float kr[HD];
    float nk = 0.f;
    #pragma unroll
    for (int d = 0; d < HD; ++d) { kr[d] = base[CC + d]; nk += kr[d]*kr[d]; }
    nk = fmaxf(sqrtf(nk), 1e-12f);
    float invk = 1.f / nk;
    #pragma unroll
    for (int d = 0; d < HD; ++d) ks[t][d] = kr[d] * invk;
    #pragma unroll
    for (int d = 0; d < HD; ++d) vs[t][d] = base[2*CC + d];
    __syncthreads();

    const float scale = 0.17677669529663687f;   // 1/sqrt(32)
    float s[NN];
    float mx = -1e30f;
    #pragma unroll 4
    for (int m = 0; m < NN; ++m) {
        float dot = 0.f;
        #pragma unroll
        for (int d = 0; d < HD; ++d) dot += q[d] * ks[m][d];
        s[m] = dot * scale;
        mx = fmaxf(mx, s[m]);
    }
    float sum = 0.f;
    #pragma unroll 4
    for (int m = 0; m < NN; ++m) { s[m] = expf(s[m] - mx); sum += s[m]; }
    float rs = 1.f / sum;
    float o[HD] = {};
    #pragma unroll 4
    for (int m = 0; m < NN; ++m) {
        float p = fminf(fmaxf(s[m] * rs, 1e-6f), 1.0f);
        #pragma unroll
        for (int d = 0; d < HD; ++d) o[d] += p * vs[m][d];
    }
    float* dst = attno + (size_t)(win * NN + t) * CC + h * HD;
    #pragma unroll
    for (int d = 0; d < HD; ++d) dst[d] = o[d];
}

// ---------------- window reverse + un-shift + residual add ----------------
__global__ __launch_bounds__(256) void rev_res_k(
    const float* __restrict__ x, const float* __restrict__ projo,
    float* __restrict__ x1)
{
    const size_t total = (size_t)NTOK * (CC/4);
    size_t idx = (size_t)blockIdx.x * blockDim.x + threadIdx.x;
    if (idx >= total) return;
    int t  = (int)(idx / (CC/4));
    int c4 = (int)(idx % (CC/4));
    int b   = t >> 14;
    int rem = t & 16383;
    int i = rem >> 7, j = rem & 127;
    int ip = (i + 128 - SHIFT) & 127;
    int jp = (j + 128 - SHIFT) & 127;
    int win = b * 256 + (ip >> 3) * 16 + (jp >> 3);
    int n   = ((ip & 7) << 3) + (jp & 7);
    float4 a = ((const float4*)x)[(size_t)t * (CC/4) + c4];
    float4 p = ((const float4*)projo)[(size_t)(win * NN + n) * (CC/4) + c4];
    float4 r;
    r.x = a.x + p.x; r.y = a.y + p.y; r.z = a.z + p.z; r.w = a.w + p.w;
    ((float4*)x1)[(size_t)t * (CC/4) + c4] = r;
}

// ---------------- host launcher ----------------
extern "C" void kernel_launch(void* const* d_in, const int* in_sizes, int n_in,
                              void* d_out, int out_size)
{
    const float* x      = (const float*)d_in[0];
    const float* qkv_w  = (const float*)d_in[1];
    const float* qkv_b  = (const float*)d_in[2];
    const float* proj_w = (const float*)d_in[3];
    const float* proj_b = (const float*)d_in[4];
    const float* n1_g   = (const float*)d_in[5];
    const float* n1_b   = (const float*)d_in[6];
    const float* n2_g   = (const float*)d_in[7];
    const float* n2_b   = (const float*)d_in[8];
    const float* w1     = (const float*)d_in[9];
    const float* b1     = (const float*)d_in[10];
    const float* w2     = (const float*)d_in[11];
    const float* b2     = (const float*)d_in[12];
    float* out = (float*)d_out;

    float *hwin, *qkv, *attno, *projo, *x1, *mlp1;
    cudaGetSymbolAddress((void**)&hwin,  g_hwin);
    cudaGetSymbolAddress((void**)&qkv,   g_qkv);
    cudaGetSymbolAddress((void**)&attno, g_attno);
    cudaGetSymbolAddress((void**)&projo, g_projo);
    cudaGetSymbolAddress((void**)&x1,    g_x1);
    cudaGetSymbolAddress((void**)&mlp1,  g_mlp1);

    // 1) LN1 + shift + window gather
    ln1_gather_k<<<NTOK/8, 256>>>(x, n1_g, n1_b, hwin);

    // 2) QKV GEMM: (262144,192) @ (576,192)^T
    sgemm_k<0><<<dim3((3*CC)/64, NTOK/64), 256>>>(hwin, qkv_w, qkv_b, nullptr, qkv,
                                                  NTOK, 3*CC, CC);

    // 3) attention per (window, head)
    attn_k<<<NWIN * HEADS, 64>>>(qkv, attno);

    // 4) proj GEMM
    sgemm_k<0><<<dim3(CC/64, NTOK/64), 256>>>(attno, proj_w, proj_b, nullptr, projo,
                                              NTOK, CC, CC);

    // 5) window reverse + un-shift + residual
    {
        size_t total = (size_t)NTOK * (CC/4);
        int blocks = (int)((total + 255) / 256);
        rev_res_k<<<blocks, 256>>>(x, projo, x1);
    }

    // 6) LN2 (reuse hwin buffer)
    ln2_k<<<NTOK/8, 256>>>(x1, n2_g, n2_b, hwin);

    // 7) MLP1 GEMM + GELU
    sgemm_k<1><<<dim3((4*CC)/64, NTOK/64), 256>>>(hwin, w1, b1, nullptr, mlp1,
                                                  NTOK, 4*CC, CC);

    // 8) MLP2 GEMM + bias + residual -> out
    sgemm_k<2><<<dim3(CC/64, NTOK/64), 256>>>(mlp1, w2, b2, x1, out,
                                              NTOK, CC, 4*CC);
}

// round 3
// speedup vs baseline: 2.1793x; 2.0576x over previous
#include <cuda_runtime.h>
#include <cuda_bf16.h>
#include <cstdint>
#include <cstdio>

// ---------------- problem constants ----------------
#define BIMG   16
#define HH     128
#define WW_    128
#define CC     192
#define HEADS  6
#define HD     32
#define WIN    8
#define SHIFT  4
#define NTOK   (BIMG * HH * WW_)              // 262144 tokens
#define NWIN   (BIMG * (HH/WIN) * (WW_/WIN))  // 4096 windows
#define NN     (WIN * WIN)                    // 64 tokens per window

// ---------------- scratch (device globals; no allocation allowed) ----------------
__device__ float g_hwin [ (size_t)NTOK * CC ];
__device__ float g_qkv  [ (size_t)NTOK * 3 * CC ];
__device__ float g_attno[ (size_t)NTOK * CC ];
__device__ float g_projo[ (size_t)NTOK * CC ];
__device__ float g_x1   [ (size_t)NTOK * CC ];
__device__ float g_mlp1 [ (size_t)NTOK * 4 * CC ];

// ---------------- helpers ----------------
__device__ __forceinline__ uint32_t tf32_of(float x) {
    uint32_t u;
    asm("cvt.rna.tf32.f32 %0, %1;" : "=r"(u) : "f"(x));
    return u;
}

__device__ __forceinline__ void mma_tf32(float c[4], const uint32_t a[4], const uint32_t b[2]) {
    asm volatile(
        "mma.sync.aligned.m16n8k8.row.col.f32.tf32.tf32.f32 "
        "{%0,%1,%2,%3}, {%4,%5,%6,%7}, {%8,%9}, {%0,%1,%2,%3};"
        : "+f"(c[0]), "+f"(c[1]), "+f"(c[2]), "+f"(c[3])
        : "r"(a[0]), "r"(a[1]), "r"(a[2]), "r"(a[3]), "r"(b[0]), "r"(b[1]));
}

// ---------------- LN1 + cyclic shift + window partition (warp per token) ----------------
__global__ __launch_bounds__(256) void ln1_gather_k(
    const float* __restrict__ x, const float* __restrict__ g,
    const float* __restrict__ beta, float* __restrict__ out)
{
    int warp = (blockIdx.x * blockDim.x + threadIdx.x) >> 5;
    int lane = threadIdx.x & 31;
    if (warp >= NTOK) return;
    int win = warp >> 6, n = warp & 63;
    int b   = win >> 8;
    int wh  = (win >> 4) & 15;
    int ww  = win & 15;
    int r   = n >> 3, c = n & 7;
    int i = (wh * WIN + r + SHIFT) & 127;
    int j = (ww * WIN + c + SHIFT) & 127;
    const float* src = x + ((size_t)b * (HH*WW_) + (size_t)i * WW_ + j) * CC;

    float v[6];
    float sum = 0.f;
    #pragma unroll
    for (int u = 0; u < 6; ++u) { v[u] = src[lane + u*32]; sum += v[u]; }
    #pragma unroll
    for (int o = 16; o; o >>= 1) sum += __shfl_xor_sync(0xffffffffu, sum, o);
    float mean = sum * (1.f/192.f);
    float var = 0.f;
    #pragma unroll
    for (int u = 0; u < 6; ++u) { float d = v[u]-mean; var += d*d; }
    #pragma unroll
    for (int o = 16; o; o >>= 1) var += __shfl_xor_sync(0xffffffffu, var, o);
    var *= (1.f/192.f);
    float rstd = rsqrtf(var + 1e-5f);
    float* dst = out + (size_t)warp * CC;
    #pragma unroll
    for (int u = 0; u < 6; ++u) {
        int ch = lane + u*32;
        dst[ch] = (v[u]-mean)*rstd*g[ch] + beta[ch];
    }
}

// ---------------- plain LN (warp per token) ----------------
__global__ __launch_bounds__(256) void ln2_k(
    const float* __restrict__ x, const float* __restrict__ g,
    const float* __restrict__ beta, float* __restrict__ out)
{
    int warp = (blockIdx.x * blockDim.x + threadIdx.x) >> 5;
    int lane = threadIdx.x & 31;
    if (warp >= NTOK) return;
    const float* src = x + (size_t)warp * CC;
    float v[6];
    float sum = 0.f;
    #pragma unroll
    for (int u = 0; u < 6; ++u) { v[u] = src[lane + u*32]; sum += v[u]; }
    #pragma unroll
    for (int o = 16; o; o >>= 1) sum += __shfl_xor_sync(0xffffffffu, sum, o);
    float mean = sum * (1.f/192.f);
    float var = 0.f;
    #pragma unroll
    for (int u = 0; u < 6; ++u) { float d = v[u]-mean; var += d*d; }
    #pragma unroll
    for (int o = 16; o; o >>= 1) var += __shfl_xor_sync(0xffffffffu, var, o);
    var *= (1.f/192.f);
    float rstd = rsqrtf(var + 1e-5f);
    float* dst = out + (size_t)warp * CC;
    #pragma unroll
    for (int u = 0; u < 6; ++u) {
        int ch = lane + u*32;
        dst[ch] = (v[u]-mean)*rstd*g[ch] + beta[ch];
    }
}

// ---------------- tf32 tensor-core GEMM: C[M,N] = A[M,K] @ B[N,K]^T + bias ----------------
// Tile: 128(M) x 64(N) per 256-thread block; warp tile 32x32 (2x m16 by 4x n8).
// EPI 0: +bias. EPI 1: +bias then exact GELU. EPI 2: +bias +resid.
template<int EPI>
__global__ __launch_bounds__(256) void mma_gemm_k(
    const float* __restrict__ A, const float* __restrict__ B,
    const float* __restrict__ bias, const float* __restrict__ resid,
    float* __restrict__ C, int M, int N, int K)
{
    __shared__ float As[128][20];   // row-major [row][k], pad 4 -> conflict-free frags
    __shared__ float Bs[64][20];    // [n][k]

    const int bm = blockIdx.y * 128;
    const int bn = blockIdx.x * 64;
    const int tid  = threadIdx.x;
    const int lane = tid & 31;
    const int warp = tid >> 5;
    const int wm = warp & 3;        // 4 M-subtiles of 32
    const int wn = warp >> 2;       // 2 N-subtiles of 32

    // global staging indices (K-step = 16)
    const int gr = tid >> 2;          // 0..63
    const int gc = (tid & 3) << 2;    // 0,4,8,12
    const float* Ap0 = A + (size_t)(bm + gr)      * K + gc;
    const float* Ap1 = A + (size_t)(bm + gr + 64) * K + gc;
    const float* Bp  = B + (size_t)(bn + gr)      * K + gc;

    float acc[2][4][4];
    #pragma unroll
    for (int i = 0; i < 2; ++i)
        #pragma unroll
        for (int j = 0; j < 4; ++j)
            #pragma unroll
            for (int r = 0; r < 4; ++r) acc[i][j][r] = 0.f;

    const int qrow = lane >> 2;     // 0..7
    const int qcol = lane & 3;      // 0..3

    for (int k0 = 0; k0 < K; k0 += 16) {
        float4 a0 = *(const float4*)(Ap0 + k0);
        float4 a1 = *(const float4*)(Ap1 + k0);
        float4 bv = *(const float4*)(Bp  + k0);
        // round to tf32 once, at staging time
        As[gr   ][gc+0] = __uint_as_float(tf32_of(a0.x));
        As[gr   ][gc+1] = __uint_as_float(tf32_of(a0.y));
        As[gr   ][gc+2] = __uint_as_float(tf32_of(a0.z));
        As[gr   ][gc+3] = __uint_as_float(tf32_of(a0.w));
        As[gr+64][gc+0] = __uint_as_float(tf32_of(a1.x));
        As[gr+64][gc+1] = __uint_as_float(tf32_of(a1.y));
        As[gr+64][gc+2] = __uint_as_float(tf32_of(a1.z));
        As[gr+64][gc+3] = __uint_as_float(tf32_of(a1.w));
        Bs[gr][gc+0] = __uint_as_float(tf32_of(bv.x));
        Bs[gr][gc+1] = __uint_as_float(tf32_of(bv.y));
        Bs[gr][gc+2] = __uint_as_float(tf32_of(bv.z));
        Bs[gr][gc+3] = __uint_as_float(tf32_of(bv.w));
        __syncthreads();

        #pragma unroll
        for (int ks = 0; ks < 16; ks += 8) {
            uint32_t afr[2][4];
            #pragma unroll
            for (int mt = 0; mt < 2; ++mt) {
                int r = wm*32 + mt*16 + qrow;
                afr[mt][0] = __float_as_uint(As[r  ][ks + qcol    ]);
                afr[mt][1] = __float_as_uint(As[r+8][ks + qcol    ]);
                afr[mt][2] = __float_as_uint(As[r  ][ks + qcol + 4]);
                afr[mt][3] = __float_as_uint(As[r+8][ks + qcol + 4]);
            }
            uint32_t bfr[4][2];
            #pragma unroll
            for (int nt = 0; nt < 4; ++nt) {
                int n = wn*32 + nt*8 + qrow;
                bfr[nt][0] = __float_as_uint(Bs[n][ks + qcol    ]);
                bfr[nt][1] = __float_as_uint(Bs[n][ks + qcol + 4]);
            }
            #pragma unroll
            for (int mt = 0; mt < 2; ++mt)
                #pragma unroll
                for (int nt = 0; nt < 4; ++nt)
                    mma_tf32(acc[mt][nt], afr[mt], bfr[nt]);
        }
        __syncthreads();
    }

    // epilogue: C frag mapping (m16n8): c0 (row=qrow, col=2*qcol), c1 col+1, c2/c3 row+8
    #pragma unroll
    for (int mt = 0; mt < 2; ++mt) {
        #pragma unroll
        for (int nt = 0; nt < 4; ++nt) {
            int row0 = bm + wm*32 + mt*16 + qrow;
            int col0 = bn + wn*32 + nt*8 + qcol*2;
            #pragma unroll
            for (int half = 0; half < 2; ++half) {
                int row = row0 + half*8;
                #pragma unroll
                for (int e = 0; e < 2; ++e) {
                    int col = col0 + e;
                    float v = acc[mt][nt][half*2 + e] + bias[col];
                    if (EPI == 1) v = 0.5f * v * (1.0f + erff(v * 0.70710678118654752f));
                    if (EPI == 2) v += resid[(size_t)row * N + col];
                    C[(size_t)row * N + col] = v;
                }
            }
        }
    }
}

// ---------------- windowed attention: one block per (window, head), 64 threads ----------------
__global__ __launch_bounds__(64) void attn_k(
    const float* __restrict__ qkv, float* __restrict__ attno)
{
    const int win = blockIdx.x / HEADS;
    const int h   = blockIdx.x % HEADS;
    const int t   = threadIdx.x;
    __shared__ float ks[NN][HD + 1];
    __shared__ float vs[NN][HD + 1];

    const float* base = qkv + (size_t)(win * NN + t) * (3*CC) + h * HD;

    float q[HD];
    float nq = 0.f;
    #pragma unroll
    for (int d = 0; d < HD; ++d) { q[d] = base[d]; nq += q[d]*q[d]; }
    nq = fmaxf(sqrtf(nq), 1e-12f);
    float invq = 1.f / nq;
    #pragma unroll
    for (int d = 0; d < HD; ++d) q[d] *= invq;

    float kr[HD];
    float nk = 0.f;
    #pragma unroll
    for (int d = 0; d < HD; ++d) { kr[d] = base[CC + d]; nk += kr[d]*kr[d]; }
    nk = fmaxf(sqrtf(nk), 1e-12f);
    float invk = 1.f / nk;
    #pragma unroll
    for (int d = 0; d < HD; ++d) ks[t][d] = kr[d] * invk;
    #pragma unroll
    for (int d = 0; d < HD; ++d) vs[t][d] = base[2*CC + d];
    __syncthreads();

    const float scale = 0.17677669529663687f;
    float s[NN];
    float mx = -1e30f;
    #pragma unroll 4
    for (int m = 0; m < NN; ++m) {
        float dot = 0.f;
        #pragma unroll
        for (int d = 0; d < HD; ++d) dot += q[d] * ks[m][d];
        s[m] = dot * scale;
        mx = fmaxf(mx, s[m]);
    }
    float sum = 0.f;
    #pragma unroll 4
    for (int m = 0; m < NN; ++m) { s[m] = expf(s[m] - mx); sum += s[m]; }
    float rs = 1.f / sum;
    float o[HD] = {};
    #pragma unroll 4
    for (int m = 0; m < NN; ++m) {
        float p = fminf(fmaxf(s[m] * rs, 1e-6f), 1.0f);
        #pragma unroll
        for (int d = 0; d < HD; ++d) o[d] += p * vs[m][d];
    }
    float* dst = attno + (size_t)(win * NN + t) * CC + h * HD;
    #pragma unroll
    for (int d = 0; d < HD; ++d) dst[d] = o[d];
}

// ---------------- window reverse + un-shift + residual add ----------------
__global__ __launch_bounds__(256) void rev_res_k(
    const float* __restrict__ x, const float* __restrict__ projo,
    float* __restrict__ x1)
{
    const size_t total = (size_t)NTOK * (CC/4);
    size_t idx = (size_t)blockIdx.x * blockDim.x + threadIdx.x;
    if (idx >= total) return;
    int t  = (int)(idx / (CC/4));
    int c4 = (int)(idx % (CC/4));
    int b   = t >> 14;
    int rem = t & 16383;
    int i = rem >> 7, j = rem & 127;
    int ip = (i + 128 - SHIFT) & 127;
    int jp = (j + 128 - SHIFT) & 127;
    int win = b * 256 + (ip >> 3) * 16 + (jp >> 3);
    int n   = ((ip & 7) << 3) + (jp & 7);
    float4 a = ((const float4*)x)[(size_t)t * (CC/4) + c4];
    float4 p = ((const float4*)projo)[(size_t)(win * NN + n) * (CC/4) + c4];
    float4 r;
    r.x = a.x + p.x; r.y = a.y + p.y; r.z = a.z + p.z; r.w = a.w + p.w;
    ((float4*)x1)[(size_t)t * (CC/4) + c4] = r;
}

// ---------------- host launcher ----------------
extern "C" void kernel_launch(void* const* d_in, const int* in_sizes, int n_in,
                              void* d_out, int out_size)
{
    const float* x      = (const float*)d_in[0];
    const float* qkv_w  = (const float*)d_in[1];
    const float* qkv_b  = (const float*)d_in[2];
    const float* proj_w = (const float*)d_in[3];
    const float* proj_b = (const float*)d_in[4];
    const float* n1_g   = (const float*)d_in[5];
    const float* n1_b   = (const float*)d_in[6];
    const float* n2_g   = (const float*)d_in[7];
    const float* n2_b   = (const float*)d_in[8];
    const float* w1     = (const float*)d_in[9];
    const float* b1     = (const float*)d_in[10];
    const float* w2     = (const float*)d_in[11];
    const float* b2     = (const float*)d_in[12];
    float* out = (float*)d_out;

    float *hwin, *qkv, *attno, *projo, *x1, *mlp1;
    cudaGetSymbolAddress((void**)&hwin,  g_hwin);
    cudaGetSymbolAddress((void**)&qkv,   g_qkv);
    cudaGetSymbolAddress((void**)&attno, g_attno);
    cudaGetSymbolAddress((void**)&projo, g_projo);
    cudaGetSymbolAddress((void**)&x1,    g_x1);
    cudaGetSymbolAddress((void**)&mlp1,  g_mlp1);

    // 1) LN1 + shift + window gather
    ln1_gather_k<<<NTOK/8, 256>>>(x, n1_g, n1_b, hwin);

    // 2) QKV GEMM: (262144,192) @ (576,192)^T
    mma_gemm_k<0><<<dim3((3*CC)/64, NTOK/128), 256>>>(hwin, qkv_w, qkv_b, nullptr, qkv,
                                                      NTOK, 3*CC, CC);

    // 3) attention per (window, head)
    attn_k<<<NWIN * HEADS, 64>>>(qkv, attno);

    // 4) proj GEMM
    mma_gemm_k<0><<<dim3(CC/64, NTOK/128), 256>>>(attno, proj_w, proj_b, nullptr, projo,
                                                  NTOK, CC, CC);

    // 5) window reverse + un-shift + residual
    {
        size_t total = (size_t)NTOK * (CC/4);
        int blocks = (int)((total + 255) / 256);
        rev_res_k<<<blocks, 256>>>(x, projo, x1);
    }

    // 6) LN2 (reuse hwin buffer)
    ln2_k<<<NTOK/8, 256>>>(x1, n2_g, n2_b, hwin);

    // 7) MLP1 GEMM + GELU
    mma_gemm_k<1><<<dim3((4*CC)/64, NTOK/128), 256>>>(hwin, w1, b1, nullptr, mlp1,
                                                      NTOK, 4*CC, CC);

    // 8) MLP2 GEMM + bias + residual -> out
    mma_gemm_k<2><<<dim3(CC/64, NTOK/128), 256>>>(mlp1, w2, b2, x1, out,
                                                  NTOK, CC, 4*CC);
}

// round 4
// speedup vs baseline: 2.2482x; 1.0316x over previous
#include <cuda_runtime.h>
#include <cuda_bf16.h>
#include <cstdint>
#include <cstdio>

// ---------------- problem constants ----------------
#define BIMG   16
#define HH     128
#define WW_    128
#define CC     192
#define HEADS  6
#define HD     32
#define WIN    8
#define SHIFT  4
#define NTOK   (BIMG * HH * WW_)              // 262144 tokens
#define NWIN   (BIMG * (HH/WIN) * (WW_/WIN))  // 4096 windows
#define NN     (WIN * WIN)                    // 64 tokens per window

// ---------------- scratch (device globals; no allocation allowed) ----------------
__device__ float g_hwin [ (size_t)NTOK * CC ];
__device__ float g_qkv  [ (size_t)NTOK * 3 * CC ];
__device__ float g_attno[ (size_t)NTOK * CC ];
__device__ float g_x1   [ (size_t)NTOK * CC ];
__device__ float g_mlp1 [ (size_t)NTOK * 4 * CC ];

// ---------------- helpers ----------------
__device__ __forceinline__ float tf32f(float x) {
    uint32_t u;
    asm("cvt.rna.tf32.f32 %0, %1;" : "=r"(u) : "f"(x));
    return __uint_as_float(u);
}

__device__ __forceinline__ void mma_tf32(float c[4], const uint32_t a[4], const uint32_t b[2]) {
    asm volatile(
        "mma.sync.aligned.m16n8k8.row.col.f32.tf32.tf32.f32 "
        "{%0,%1,%2,%3}, {%4,%5,%6,%7}, {%8,%9}, {%0,%1,%2,%3};"
        : "+f"(c[0]), "+f"(c[1]), "+f"(c[2]), "+f"(c[3])
        : "r"(a[0]), "r"(a[1]), "r"(a[2]), "r"(a[3]), "r"(b[0]), "r"(b[1]));
}

// ---------------- LN1 + cyclic shift + window partition (warp per token) ----------------
__global__ __launch_bounds__(256) void ln1_gather_k(
    const float* __restrict__ x, const float* __restrict__ g,
    const float* __restrict__ beta, float* __restrict__ out)
{
    int warp = (blockIdx.x * blockDim.x + threadIdx.x) >> 5;
    int lane = threadIdx.x & 31;
    if (warp >= NTOK) return;
    int win = warp >> 6, n = warp & 63;
    int b   = win >> 8;
    int wh  = (win >> 4) & 15;
    int ww  = win & 15;
    int r   = n >> 3, c = n & 7;
    int i = (wh * WIN + r + SHIFT) & 127;
    int j = (ww * WIN + c + SHIFT) & 127;
    const float* src = x + ((size_t)b * (HH*WW_) + (size_t)i * WW_ + j) * CC;

    float v[6];
    float sum = 0.f;
    #pragma unroll
    for (int u = 0; u < 6; ++u) { v[u] = src[lane + u*32]; sum += v[u]; }
    #pragma unroll
    for (int o = 16; o; o >>= 1) sum += __shfl_xor_sync(0xffffffffu, sum, o);
    float mean = sum * (1.f/192.f);
    float var = 0.f;
    #pragma unroll
    for (int u = 0; u < 6; ++u) { float d = v[u]-mean; var += d*d; }
    #pragma unroll
    for (int o = 16; o; o >>= 1) var += __shfl_xor_sync(0xffffffffu, var, o);
    var *= (1.f/192.f);
    float rstd = rsqrtf(var + 1e-5f);
    float* dst = out + (size_t)warp * CC;
    #pragma unroll
    for (int u = 0; u < 6; ++u) {
        int ch = lane + u*32;
        dst[ch] = (v[u]-mean)*rstd*g[ch] + beta[ch];
    }
}

// ---------------- plain LN (warp per token) ----------------
__global__ __launch_bounds__(256) void ln2_k(
    const float* __restrict__ x, const float* __restrict__ g,
    const float* __restrict__ beta, float* __restrict__ out)
{
    int warp = (blockIdx.x * blockDim.x + threadIdx.x) >> 5;
    int lane = threadIdx.x & 31;
    if (warp >= NTOK) return;
    const float* src = x + (size_t)warp * CC;
    float v[6];
    float sum = 0.f;
    #pragma unroll
    for (int u = 0; u < 6; ++u) { v[u] = src[lane + u*32]; sum += v[u]; }
    #pragma unroll
    for (int o = 16; o; o >>= 1) sum += __shfl_xor_sync(0xffffffffu, sum, o);
    float mean = sum * (1.f/192.f);
    float var = 0.f;
    #pragma unroll
    for (int u = 0; u < 6; ++u) { float d = v[u]-mean; var += d*d; }
    #pragma unroll
    for (int o = 16; o; o >>= 1) var += __shfl_xor_sync(0xffffffffu, var, o);
    var *= (1.f/192.f);
    float rstd = rsqrtf(var + 1e-5f);
    float* dst = out + (size_t)warp * CC;
    #pragma unroll
    for (int u = 0; u < 6; ++u) {
        int ch = lane + u*32;
        dst[ch] = (v[u]-mean)*rstd*g[ch] + beta[ch];
    }
}

// ---------------- tf32 tensor-core GEMM, double-buffered, paired frag layout ----------------
// C[M,N] = A[M,K] @ B[N,K]^T + bias.  Tile 128x64, 8 warps of 32x32.
// A pair layout: AsP[(band*16 + k)*12 + qrow] = {A[band*16+qrow][k], A[band*16+8+qrow][k]}
// B pair layout: BsP[n*12 + kc*4 + qcol]     = {B[n][kc*8+qcol],   B[n][kc*8+qcol+4]}
// EPI 0: +bias. EPI 1: +bias,GELU. EPI 2: +bias,+resid. EPI 3: +bias,+resid with
// window-reverse row remap (writes token order).
template<int EPI>
__global__ __launch_bounds__(256) void mma_gemm2_k(
    const float* __restrict__ A, const float* __restrict__ B,
    const float* __restrict__ bias, const float* __restrict__ resid,
    float* __restrict__ C, int M, int N, int K)
{
    __shared__ float2 AsP[2][8*16*12];
    __shared__ float2 BsP[2][64*12];

    const int bm = blockIdx.y * 128;
    const int bn = blockIdx.x * 64;
    const int tid  = threadIdx.x;
    const int lane = tid & 31;
    const int warp = tid >> 5;
    const int wm = warp & 3;
    const int wn = warp >> 2;
    const int qrow = lane >> 2;
    const int qcol = lane & 3;

    const int gr = tid >> 2;           // 0..63
    const int gc = (tid & 3) << 2;     // 0,4,8,12
    const int band0 = gr >> 4;         // 0..3
    const int qr0   = gr & 7;
    const int h0    = (gr >> 3) & 1;

    const float* Ap0 = A + (size_t)(bm + gr)      * K + gc;
    const float* Ap1 = A + (size_t)(bm + gr + 64) * K + gc;
    const float* Bp  = B + (size_t)(bn + gr)      * K + gc;

    float acc[2][4][4];
    #pragma unroll
    for (int i = 0; i < 2; ++i)
        #pragma unroll
        for (int j = 0; j < 4; ++j)
            #pragma unroll
            for (int r = 0; r < 4; ++r) acc[i][j][r] = 0.f;

    float4 ra0 = *(const float4*)(Ap0);
    float4 ra1 = *(const float4*)(Ap1);
    float4 rb  = *(const float4*)(Bp);

    // stage into buffer 0
    {
        float va0[4] = {ra0.x, ra0.y, ra0.z, ra0.w};
        float va1[4] = {ra1.x, ra1.y, ra1.z, ra1.w};
        float vb [4] = {rb.x,  rb.y,  rb.z,  rb.w};
        #pragma unroll
        for (int j = 0; j < 4; ++j) {
            int k = gc + j;
            ((float*)&AsP[0][(band0*16 + k)*12 + qr0])[h0]     = tf32f(va0[j]);
            ((float*)&AsP[0][((band0+4)*16 + k)*12 + qr0])[h0] = tf32f(va1[j]);
            int kc = k >> 3, qc = k & 3, hb = (k >> 2) & 1;
            ((float*)&BsP[0][gr*12 + kc*4 + qc])[hb]           = tf32f(vb[j]);
        }
    }
    __syncthreads();

    int buf = 0;
    int k0 = 0;
    while (true) {
        bool more = (k0 + 16) < K;
        if (more) {
            ra0 = *(const float4*)(Ap0 + k0 + 16);
            ra1 = *(const float4*)(Ap1 + k0 + 16);
            rb  = *(const float4*)(Bp  + k0 + 16);
        }
        // compute on current buffer
        #pragma unroll
        for (int kc = 0; kc < 2; ++kc) {
            uint32_t afr[2][4];
            #pragma unroll
            for (int mt = 0; mt < 2; ++mt) {
                int band = wm*2 + mt;
                float2 lo = AsP[buf][(band*16 + kc*8 + qcol    )*12 + qrow];
                float2 hi = AsP[buf][(band*16 + kc*8 + qcol + 4)*12 + qrow];
                afr[mt][0] = __float_as_uint(lo.x);
                afr[mt][1] = __float_as_uint(lo.y);
                afr[mt][2] = __float_as_uint(hi.x);
                afr[mt][3] = __float_as_uint(hi.y);
            }
            uint32_t bfr[4][2];
            #pragma unroll
            for (int nt = 0; nt < 4; ++nt) {
                int n = wn*32 + nt*8 + qrow;
                float2 bb = BsP[buf][n*12 + kc*4 + qcol];
                bfr[nt][0] = __float_as_uint(bb.x);
                bfr[nt][1] = __float_as_uint(bb.y);
            }
            #pragma unroll
            for (int mt = 0; mt < 2; ++mt)
                #pragma unroll
                for (int nt = 0; nt < 4; ++nt)
                    mma_tf32(acc[mt][nt], afr[mt], bfr[nt]);
        }
        if (!more) break;
        // stage next into other buffer
        {
            int ob = buf ^ 1;
            float va0[4] = {ra0.x, ra0.y, ra0.z, ra0.w};
            float va1[4] = {ra1.x, ra1.y, ra1.z, ra1.w};
            float vb [4] = {rb.x,  rb.y,  rb.z,  rb.w};
            #pragma unroll
            for (int j = 0; j < 4; ++j) {
                int k = gc + j;
                ((float*)&AsP[ob][(band0*16 + k)*12 + qr0])[h0]     = tf32f(va0[j]);
                ((float*)&AsP[ob][((band0+4)*16 + k)*12 + qr0])[h0] = tf32f(va1[j]);
                int kc = k >> 3, qc = k & 3, hb = (k >> 2) & 1;
                ((float*)&BsP[ob][gr*12 + kc*4 + qc])[hb]           = tf32f(vb[j]);
            }
        }
        __syncthreads();
        buf ^= 1;
        k0 += 16;
    }

    // epilogue
    #pragma unroll
    for (int mt = 0; mt < 2; ++mt) {
        #pragma unroll
        for (int half = 0; half < 2; ++half) {
            int row = bm + wm*32 + mt*16 + qrow + half*8;
            size_t orow;
            if (EPI == 3) {
                int win = row >> 6, nn = row & 63;
                int b   = win >> 8;
                int wh  = (win >> 4) & 15;
                int ww  = win & 15;
                int rr  = nn >> 3, cc = nn & 7;
                int i = (wh*WIN + rr + SHIFT) & 127;
                int j = (ww*WIN + cc + SHIFT) & 127;
                orow = (size_t)b * (HH*WW_) + (size_t)i * WW_ + j;
            } else {
                orow = (size_t)row;
            }
            #pragma unroll
            for (int nt = 0; nt < 4; ++nt) {
                int col0 = bn + wn*32 + nt*8 + qcol*2;
                #pragma unroll
                for (int e = 0; e < 2; ++e) {
                    int col = col0 + e;
                    float v = acc[mt][nt][half*2 + e] + bias[col];
                    if (EPI == 1) v = 0.5f * v * (1.0f + erff(v * 0.70710678118654752f));
                    if (EPI == 2 || EPI == 3) v += resid[orow * N + col];
                    C[orow * N + col] = v;
                }
            }
        }
    }
}

// ---------------- windowed attention: block per (window, head), 64 threads ----------------
// Logits bounded (|s| <= 0.177 since q,k l2-normalized): no max-subtract needed,
// clip(1e-6,1) is provably a no-op, exp via degree-5 polynomial.
__global__ __launch_bounds__(64) void attn_k(
    const float* __restrict__ qkv, float* __restrict__ attno)
{
    const int win = blockIdx.x / HEADS;
    const int h   = blockIdx.x % HEADS;
    const int t   = threadIdx.x;
    __shared__ float4 ks4[NN][9];   // pad to 9 float4 for conflict-free staging
    __shared__ float4 vs4[NN][9];

    const float4* base = (const float4*)(qkv + (size_t)(win * NN + t) * (3*CC) + h * HD);

    float4 q4[8];
    float nq = 0.f;
    #pragma unroll
    for (int i = 0; i < 8; ++i) {
        q4[i] = base[i];
        nq += q4[i].x*q4[i].x + q4[i].y*q4[i].y + q4[i].z*q4[i].z + q4[i].w*q4[i].w;
    }
    const float scale = 0.17677669529663687f;
    float invq = scale / fmaxf(sqrtf(nq), 1e-12f);
    #pragma unroll
    for (int i = 0; i < 8; ++i) {
        q4[i].x *= invq; q4[i].y *= invq; q4[i].z *= invq; q4[i].w *= invq;
    }

    {
        float4 kk[8];
        float nk = 0.f;
        #pragma unroll
        for (int i = 0; i < 8; ++i) {
            kk[i] = base[(CC/4) + i];
            nk += kk[i].x*kk[i].x + kk[i].y*kk[i].y + kk[i].z*kk[i].z + kk[i].w*kk[i].w;
        }
        float invk = 1.f / fmaxf(sqrtf(nk), 1e-12f);
        #pragma unroll
        for (int i = 0; i < 8; ++i) {
            float4 o;
            o.x = kk[i].x*invk; o.y = kk[i].y*invk; o.z = kk[i].z*invk; o.w = kk[i].w*invk;
            ks4[t][i] = o;
        }
        #pragma unroll
        for (int i = 0; i < 8; ++i) vs4[t][i] = base[(2*CC/4) + i];
    }
    __syncthreads();

    float sum = 0.f;
    float4 o4[8];
    #pragma unroll
    for (int i = 0; i < 8; ++i) { o4[i].x = 0.f; o4[i].y = 0.f; o4[i].z = 0.f; o4[i].w = 0.f; }

    #pragma unroll 8
    for (int m = 0; m < NN; ++m) {
        float d0 = 0.f, d1 = 0.f, d2 = 0.f, d3 = 0.f;
        #pragma unroll
        for (int i = 0; i < 8; ++i) {
            float4 kk = ks4[m][i];
            d0 += q4[i].x * kk.x;
            d1 += q4[i].y * kk.y;
            d2 += q4[i].z * kk.z;
            d3 += q4[i].w * kk.w;
        }
        float xx = (d0 + d1) + (d2 + d3);
        // exp(x), |x| <= 0.1768: degree-5 Taylor (rel err < 5e-9)
        float e = 8.3333333e-3f;            // 1/120
        e = e * xx + 4.1666667e-2f;         // 1/24
        e = e * xx + 1.6666667e-1f;         // 1/6
        e = e * xx + 0.5f;
        e = e * xx + 1.0f;
        e = e * xx + 1.0f;
        sum += e;
        #pragma unroll
        for (int i = 0; i < 8; ++i) {
            float4 vv = vs4[m][i];
            o4[i].x += e * vv.x;
            o4[i].y += e * vv.y;
            o4[i].z += e * vv.z;
            o4[i].w += e * vv.w;
        }
    }
    float rs = 1.f / sum;
    float4* dst = (float4*)(attno + (size_t)(win * NN + t) * CC + h * HD);
    #pragma unroll
    for (int i = 0; i < 8; ++i) {
        float4 o;
        o.x = o4[i].x * rs; o.y = o4[i].y * rs; o.z = o4[i].z * rs; o.w = o4[i].w * rs;
        dst[i] = o;
    }
}

// ---------------- host launcher ----------------
extern "C" void kernel_launch(void* const* d_in, const int* in_sizes, int n_in,
                              void* d_out, int out_size)
{
    const float* x      = (const float*)d_in[0];
    const float* qkv_w  = (const float*)d_in[1];
    const float* qkv_b  = (const float*)d_in[2];
    const float* proj_w = (const float*)d_in[3];
    const float* proj_b = (const float*)d_in[4];
    const float* n1_g   = (const float*)d_in[5];
    const float* n1_b   = (const float*)d_in[6];
    const float* n2_g   = (const float*)d_in[7];
    const float* n2_b   = (const float*)d_in[8];
    const float* w1     = (const float*)d_in[9];
    const float* b1     = (const float*)d_in[10];
    const float* w2     = (const float*)d_in[11];
    const float* b2     = (const float*)d_in[12];
    float* out = (float*)d_out;

    float *hwin, *qkv, *attno, *x1, *mlp1;
    cudaGetSymbolAddress((void**)&hwin,  g_hwin);
    cudaGetSymbolAddress((void**)&qkv,   g_qkv);
    cudaGetSymbolAddress((void**)&attno, g_attno);
    cudaGetSymbolAddress((void**)&x1,    g_x1);
    cudaGetSymbolAddress((void**)&mlp1,  g_mlp1);

    // 1) LN1 + shift + window gather
    ln1_gather_k<<<NTOK/8, 256>>>(x, n1_g, n1_b, hwin);

    // 2) QKV GEMM: (262144,192) @ (576,192)^T
    mma_gemm2_k<0><<<dim3((3*CC)/64, NTOK/128), 256>>>(hwin, qkv_w, qkv_b, nullptr, qkv,
                                                       NTOK, 3*CC, CC);

    // 3) attention per (window, head)
    attn_k<<<NWIN * HEADS, 64>>>(qkv, attno);

    // 4) proj GEMM + window reverse + residual -> x1 (token order)
    mma_gemm2_k<3><<<dim3(CC/64, NTOK/128), 256>>>(attno, proj_w, proj_b, x, x1,
                                                   NTOK, CC, CC);

    // 5) LN2 (reuse hwin buffer)
    ln2_k<<<NTOK/8, 256>>>(x1, n2_g, n2_b, hwin);

    // 6) MLP1 GEMM + GELU
    mma_gemm2_k<1><<<dim3((4*CC)/64, NTOK/128), 256>>>(hwin, w1, b1, nullptr, mlp1,
                                                       NTOK, 4*CC, CC);

    // 7) MLP2 GEMM + bias + residual -> out
    mma_gemm2_k<2><<<dim3(CC/64, NTOK/128), 256>>>(mlp1, w2, b2, x1, out,
                                                   NTOK, CC, 4*CC);
}

// round 5
// speedup vs baseline: 2.4743x; 1.1005x over previous
#include <cuda_runtime.h>
#include <cuda_bf16.h>
#include <cstdint>
#include <cstdio>

// ---------------- problem constants ----------------
#define BIMG   16
#define HH     128
#define WW_    128
#define CC     192
#define HEADS  6
#define HD     32
#define WIN    8
#define SHIFT  4
#define NTOK   (BIMG * HH * WW_)              // 262144 tokens
#define NWIN   (BIMG * (HH/WIN) * (WW_/WIN))  // 4096 windows
#define NN     (WIN * WIN)                    // 64 tokens per window

// ---------------- scratch (device globals; no allocation allowed) ----------------
__device__ float g_hwin [ (size_t)NTOK * CC ];
__device__ float g_qkv  [ (size_t)NTOK * 3 * CC ];
__device__ float g_attno[ (size_t)NTOK * CC ];
__device__ float g_x1   [ (size_t)NTOK * CC ];
__device__ float g_mlp1 [ (size_t)NTOK * 4 * CC ];

// ---------------- helpers ----------------
__device__ __forceinline__ float tf32f(float x) {
    uint32_t u;
    asm("cvt.rna.tf32.f32 %0, %1;" : "=r"(u) : "f"(x));
    return __uint_as_float(u);
}

__device__ __forceinline__ void mma_tf32(float c[4], const uint32_t a[4], const uint32_t b[2]) {
    asm volatile(
        "mma.sync.aligned.m16n8k8.row.col.f32.tf32.tf32.f32 "
        "{%0,%1,%2,%3}, {%4,%5,%6,%7}, {%8,%9}, {%0,%1,%2,%3};"
        : "+f"(c[0]), "+f"(c[1]), "+f"(c[2]), "+f"(c[3])
        : "r"(a[0]), "r"(a[1]), "r"(a[2]), "r"(a[3]), "r"(b[0]), "r"(b[1]));
}

// ---------------- LN1 + cyclic shift + window partition (warp per token) ----------------
__global__ __launch_bounds__(256) void ln1_gather_k(
    const float* __restrict__ x, const float* __restrict__ g,
    const float* __restrict__ beta, float* __restrict__ out)
{
    int warp = (blockIdx.x * blockDim.x + threadIdx.x) >> 5;
    int lane = threadIdx.x & 31;
    if (warp >= NTOK) return;
    int win = warp >> 6, n = warp & 63;
    int b   = win >> 8;
    int wh  = (win >> 4) & 15;
    int ww  = win & 15;
    int r   = n >> 3, c = n & 7;
    int i = (wh * WIN + r + SHIFT) & 127;
    int j = (ww * WIN + c + SHIFT) & 127;
    const float* src = x + ((size_t)b * (HH*WW_) + (size_t)i * WW_ + j) * CC;

    float v[6];
    float sum = 0.f;
    #pragma unroll
    for (int u = 0; u < 6; ++u) { v[u] = src[lane + u*32]; sum += v[u]; }
    #pragma unroll
    for (int o = 16; o; o >>= 1) sum += __shfl_xor_sync(0xffffffffu, sum, o);
    float mean = sum * (1.f/192.f);
    float var = 0.f;
    #pragma unroll
    for (int u = 0; u < 6; ++u) { float d = v[u]-mean; var += d*d; }
    #pragma unroll
    for (int o = 16; o; o >>= 1) var += __shfl_xor_sync(0xffffffffu, var, o);
    var *= (1.f/192.f);
    float rstd = rsqrtf(var + 1e-5f);
    float* dst = out + (size_t)warp * CC;
    #pragma unroll
    for (int u = 0; u < 6; ++u) {
        int ch = lane + u*32;
        dst[ch] = (v[u]-mean)*rstd*g[ch] + beta[ch];
    }
}

// ---------------- plain LN (warp per token) ----------------
__global__ __launch_bounds__(256) void ln2_k(
    const float* __restrict__ x, const float* __restrict__ g,
    const float* __restrict__ beta, float* __restrict__ out)
{
    int warp = (blockIdx.x * blockDim.x + threadIdx.x) >> 5;
    int lane = threadIdx.x & 31;
    if (warp >= NTOK) return;
    const float* src = x + (size_t)warp * CC;
    float v[6];
    float sum = 0.f;
    #pragma unroll
    for (int u = 0; u < 6; ++u) { v[u] = src[lane + u*32]; sum += v[u]; }
    #pragma unroll
    for (int o = 16; o; o >>= 1) sum += __shfl_xor_sync(0xffffffffu, sum, o);
    float mean = sum * (1.f/192.f);
    float var = 0.f;
    #pragma unroll
    for (int u = 0; u < 6; ++u) { float d = v[u]-mean; var += d*d; }
    #pragma unroll
    for (int o = 16; o; o >>= 1) var += __shfl_xor_sync(0xffffffffu, var, o);
    var *= (1.f/192.f);
    float rstd = rsqrtf(var + 1e-5f);
    float* dst = out + (size_t)warp * CC;
    #pragma unroll
    for (int u = 0; u < 6; ++u) {
        int ch = lane + u*32;
        dst[ch] = (v[u]-mean)*rstd*g[ch] + beta[ch];
    }
}

// ---------------- tf32 tensor-core GEMM (R2 proven layout + double buffering) ----------------
// C[M,N] = A[M,K] @ B[N,K]^T + bias.  Tile 128x64, 8 warps of 32x32 (2x m16, 4x n8).
// smem layout [row][k] with k-pad 20 -> conflict-free scalar frag loads.
// EPI 0: +bias. EPI 1: +bias,GELU. EPI 2: +bias,+resid. EPI 3: +bias,+resid with
// window-reverse row remap (writes token order).
template<int EPI>
__global__ __launch_bounds__(256) void mma_gemm_k(
    const float* __restrict__ A, const float* __restrict__ B,
    const float* __restrict__ bias, const float* __restrict__ resid,
    float* __restrict__ C, int M, int N, int K)
{
    __shared__ float As[2][128][20];
    __shared__ float Bs[2][64][20];

    const int bm = blockIdx.y * 128;
    const int bn = blockIdx.x * 64;
    const int tid  = threadIdx.x;
    const int lane = tid & 31;
    const int warp = tid >> 5;
    const int wm = warp & 3;        // 4 M-subtiles of 32
    const int wn = warp >> 2;       // 2 N-subtiles of 32
    const int qrow = lane >> 2;     // 0..7
    const int qcol = lane & 3;      // 0..3

    const int gr = tid >> 2;          // 0..63
    const int gc = (tid & 3) << 2;    // 0,4,8,12
    const float* Ap0 = A + (size_t)(bm + gr)      * K + gc;
    const float* Ap1 = A + (size_t)(bm + gr + 64) * K + gc;
    const float* Bp  = B + (size_t)(bn + gr)      * K + gc;

    float acc[2][4][4];
    #pragma unroll
    for (int i = 0; i < 2; ++i)
        #pragma unroll
        for (int j = 0; j < 4; ++j)
            #pragma unroll
            for (int r = 0; r < 4; ++r) acc[i][j][r] = 0.f;

    float4 ra0 = *(const float4*)(Ap0);
    float4 ra1 = *(const float4*)(Ap1);
    float4 rb  = *(const float4*)(Bp);

    // stage into buffer 0
    As[0][gr   ][gc+0] = tf32f(ra0.x);
    As[0][gr   ][gc+1] = tf32f(ra0.y);
    As[0][gr   ][gc+2] = tf32f(ra0.z);
    As[0][gr   ][gc+3] = tf32f(ra0.w);
    As[0][gr+64][gc+0] = tf32f(ra1.x);
    As[0][gr+64][gc+1] = tf32f(ra1.y);
    As[0][gr+64][gc+2] = tf32f(ra1.z);
    As[0][gr+64][gc+3] = tf32f(ra1.w);
    Bs[0][gr][gc+0] = tf32f(rb.x);
    Bs[0][gr][gc+1] = tf32f(rb.y);
    Bs[0][gr][gc+2] = tf32f(rb.z);
    Bs[0][gr][gc+3] = tf32f(rb.w);
    __syncthreads();

    int buf = 0;
    for (int k0 = 0; ; k0 += 16) {
        const bool more = (k0 + 16) < K;
        if (more) {
            ra0 = *(const float4*)(Ap0 + k0 + 16);
            ra1 = *(const float4*)(Ap1 + k0 + 16);
            rb  = *(const float4*)(Bp  + k0 + 16);
        }
        #pragma unroll
        for (int ks = 0; ks < 16; ks += 8) {
            uint32_t afr[2][4];
            #pragma unroll
            for (int mt = 0; mt < 2; ++mt) {
                int r = wm*32 + mt*16 + qrow;
                afr[mt][0] = __float_as_uint(As[buf][r  ][ks + qcol    ]);
                afr[mt][1] = __float_as_uint(As[buf][r+8][ks + qcol    ]);
                afr[mt][2] = __float_as_uint(As[buf][r  ][ks + qcol + 4]);
                afr[mt][3] = __float_as_uint(As[buf][r+8][ks + qcol + 4]);
            }
            uint32_t bfr[4][2];
            #pragma unroll
            for (int nt = 0; nt < 4; ++nt) {
                int n = wn*32 + nt*8 + qrow;
                bfr[nt][0] = __float_as_uint(Bs[buf][n][ks + qcol    ]);
                bfr[nt][1] = __float_as_uint(Bs[buf][n][ks + qcol + 4]);
            }
            #pragma unroll
            for (int mt = 0; mt < 2; ++mt)
                #pragma unroll
                for (int nt = 0; nt < 4; ++nt)
                    mma_tf32(acc[mt][nt], afr[mt], bfr[nt]);
        }
        if (!more) break;
        const int ob = buf ^ 1;
        As[ob][gr   ][gc+0] = tf32f(ra0.x);
        As[ob][gr   ][gc+1] = tf32f(ra0.y);
        As[ob][gr   ][gc+2] = tf32f(ra0.z);
        As[ob][gr   ][gc+3] = tf32f(ra0.w);
        As[ob][gr+64][gc+0] = tf32f(ra1.x);
        As[ob][gr+64][gc+1] = tf32f(ra1.y);
        As[ob][gr+64][gc+2] = tf32f(ra1.z);
        As[ob][gr+64][gc+3] = tf32f(ra1.w);
        Bs[ob][gr][gc+0] = tf32f(rb.x);
        Bs[ob][gr][gc+1] = tf32f(rb.y);
        Bs[ob][gr][gc+2] = tf32f(rb.z);
        Bs[ob][gr][gc+3] = tf32f(rb.w);
        __syncthreads();
        buf = ob;
    }

    // epilogue: m16n8 frag -> c0 (row=qrow,col=2*qcol), c1 col+1, c2/c3 row+8
    #pragma unroll
    for (int mt = 0; mt < 2; ++mt) {
        #pragma unroll
        for (int half = 0; half < 2; ++half) {
            int row = bm + wm*32 + mt*16 + qrow + half*8;
            size_t orow;
            if (EPI == 3) {
                int win = row >> 6, nn = row & 63;
                int b   = win >> 8;
                int wh  = (win >> 4) & 15;
                int ww  = win & 15;
                int rr  = nn >> 3, cc = nn & 7;
                int i = (wh*WIN + rr + SHIFT) & 127;
                int j = (ww*WIN + cc + SHIFT) & 127;
                orow = (size_t)b * (HH*WW_) + (size_t)i * WW_ + j;
            } else {
                orow = (size_t)row;
            }
            #pragma unroll
            for (int nt = 0; nt < 4; ++nt) {
                int col0 = bn + wn*32 + nt*8 + qcol*2;
                #pragma unroll
                for (int e = 0; e < 2; ++e) {
                    int col = col0 + e;
                    float v = acc[mt][nt][half*2 + e] + bias[col];
                    if (EPI == 1) v = 0.5f * v * (1.0f + erff(v * 0.70710678118654752f));
                    if (EPI == 2 || EPI == 3) v += resid[orow * N + col];
                    C[orow * N + col] = v;
                }
            }
        }
    }
}

// ---------------- windowed attention: block per (window, head), 64 threads ----------------
// Logits bounded (|s| <= 0.177 since q,k l2-normalized): no max-subtract needed,
// clip(1e-6,1) is provably a no-op, exp via degree-5 polynomial.
__global__ __launch_bounds__(64) void attn_k(
    const float* __restrict__ qkv, float* __restrict__ attno)
{
    const int win = blockIdx.x / HEADS;
    const int h   = blockIdx.x % HEADS;
    const int t   = threadIdx.x;
    __shared__ float4 ks4[NN][9];
    __shared__ float4 vs4[NN][9];

    const float4* base = (const float4*)(qkv + (size_t)(win * NN + t) * (3*CC) + h * HD);

    float4 q4[8];
    float nq = 0.f;
    #pragma unroll
    for (int i = 0; i < 8; ++i) {
        q4[i] = base[i];
        nq += q4[i].x*q4[i].x + q4[i].y*q4[i].y + q4[i].z*q4[i].z + q4[i].w*q4[i].w;
    }
    const float scale = 0.17677669529663687f;
    float invq = scale / fmaxf(sqrtf(nq), 1e-12f);
    #pragma unroll
    for (int i = 0; i < 8; ++i) {
        q4[i].x *= invq; q4[i].y *= invq; q4[i].z *= invq; q4[i].w *= invq;
    }

    {
        float4 kk[8];
        float nk = 0.f;
        #pragma unroll
        for (int i = 0; i < 8; ++i) {
            kk[i] = base[(CC/4) + i];
            nk += kk[i].x*kk[i].x + kk[i].y*kk[i].y + kk[i].z*kk[i].z + kk[i].w*kk[i].w;
        }
        float invk = 1.f / fmaxf(sqrtf(nk), 1e-12f);
        #pragma unroll
        for (int i = 0; i < 8; ++i) {
            float4 o;
            o.x = kk[i].x*invk; o.y = kk[i].y*invk; o.z = kk[i].z*invk; o.w = kk[i].w*invk;
            ks4[t][i] = o;
        }
        #pragma unroll
        for (int i = 0; i < 8; ++i) vs4[t][i] = base[(2*CC/4) + i];
    }
    __syncthreads();

    float sum = 0.f;
    float4 o4[8];
    #pragma unroll
    for (int i = 0; i < 8; ++i) { o4[i].x = 0.f; o4[i].y = 0.f; o4[i].z = 0.f; o4[i].w = 0.f; }

    #pragma unroll 8
    for (int m = 0; m < NN; ++m) {
        float d0 = 0.f, d1 = 0.f, d2 = 0.f, d3 = 0.f;
        #pragma unroll
        for (int i = 0; i < 8; ++i) {
            float4 kk = ks4[m][i];
            d0 += q4[i].x * kk.x;
            d1 += q4[i].y * kk.y;
            d2 += q4[i].z * kk.z;
            d3 += q4[i].w * kk.w;
        }
        float xx = (d0 + d1) + (d2 + d3);
        float e = 8.3333333e-3f;
        e = e * xx + 4.1666667e-2f;
        e = e * xx + 1.6666667e-1f;
        e = e * xx + 0.5f;
        e = e * xx + 1.0f;
        e = e * xx + 1.0f;
        sum += e;
        #pragma unroll
        for (int i = 0; i < 8; ++i) {
            float4 vv = vs4[m][i];
            o4[i].x += e * vv.x;
            o4[i].y += e * vv.y;
            o4[i].z += e * vv.z;
            o4[i].w += e * vv.w;
        }
    }
    float rs = 1.f / sum;
    float4* dst = (float4*)(attno + (size_t)(win * NN + t) * CC + h * HD);
    #pragma unroll
    for (int i = 0; i < 8; ++i) {
        float4 o;
        o.x = o4[i].x * rs; o.y = o4[i].y * rs; o.z = o4[i].z * rs; o.w = o4[i].w * rs;
        dst[i] = o;
    }
}

// ---------------- host launcher ----------------
extern "C" void kernel_launch(void* const* d_in, const int* in_sizes, int n_in,
                              void* d_out, int out_size)
{
    const float* x      = (const float*)d_in[0];
    const float* qkv_w  = (const float*)d_in[1];
    const float* qkv_b  = (const float*)d_in[2];
    const float* proj_w = (const float*)d_in[3];
    const float* proj_b = (const float*)d_in[4];
    const float* n1_g   = (const float*)d_in[5];
    const float* n1_b   = (const float*)d_in[6];
    const float* n2_g   = (const float*)d_in[7];
    const float* n2_b   = (const float*)d_in[8];
    const float* w1     = (const float*)d_in[9];
    const float* b1     = (const float*)d_in[10];
    const float* w2     = (const float*)d_in[11];
    const float* b2     = (const float*)d_in[12];
    float* out = (float*)d_out;

    float *hwin, *qkv, *attno, *x1, *mlp1;
    cudaGetSymbolAddress((void**)&hwin,  g_hwin);
    cudaGetSymbolAddress((void**)&qkv,   g_qkv);
    cudaGetSymbolAddress((void**)&attno, g_attno);
    cudaGetSymbolAddress((void**)&x1,    g_x1);
    cudaGetSymbolAddress((void**)&mlp1,  g_mlp1);

    // 1) LN1 + shift + window gather
    ln1_gather_k<<<NTOK/8, 256>>>(x, n1_g, n1_b, hwin);

    // 2) QKV GEMM: (262144,192) @ (576,192)^T
    mma_gemm_k<0><<<dim3((3*CC)/64, NTOK/128), 256>>>(hwin, qkv_w, qkv_b, nullptr, qkv,
                                                      NTOK, 3*CC, CC);

    // 3) attention per (window, head)
    attn_k<<<NWIN * HEADS, 64>>>(qkv, attno);

    // 4) proj GEMM + window reverse + residual -> x1 (token order)
    mma_gemm_k<3><<<dim3(CC/64, NTOK/128), 256>>>(attno, proj_w, proj_b, x, x1,
                                                  NTOK, CC, CC);

    // 5) LN2
    ln2_k<<<NTOK/8, 256>>>(x1, n2_g, n2_b, hwin);

    // 6) MLP1 GEMM + GELU
    mma_gemm_k<1><<<dim3((4*CC)/64, NTOK/128), 256>>>(hwin, w1, b1, nullptr, mlp1,
                                                      NTOK, 4*CC, CC);

    // 7) MLP2 GEMM + bias + residual -> out
    mma_gemm_k<2><<<dim3(CC/64, NTOK/128), 256>>>(mlp1, w2, b2, x1, out,
                                                  NTOK, CC, 4*CC);
}

// round 6
// speedup vs baseline: 2.6589x; 1.0746x over previous
#include <cuda_runtime.h>
#include <cuda_bf16.h>
#include <cstdint>
#include <cstdio>

// ---------------- problem constants ----------------
#define BIMG   16
#define HH     128
#define WW_    128
#define CC     192
#define HEADS  6
#define HD     32
#define WIN    8
#define SHIFT  4
#define NTOK   (BIMG * HH * WW_)              // 262144 tokens
#define NWIN   (BIMG * (HH/WIN) * (WW_/WIN))  // 4096 windows
#define NN     (WIN * WIN)                    // 64 tokens per window

// ---------------- scratch ----------------
__device__ float g_hwin [ (size_t)NTOK * CC ];
__device__ float g_qkv  [ (size_t)NTOK * 3 * CC ];
__device__ float g_attno[ (size_t)NTOK * CC ];
__device__ float g_x1   [ (size_t)NTOK * CC ];

// ---------------- helpers ----------------
__device__ __forceinline__ float tf32f(float x) {
    uint32_t u;
    asm("cvt.rna.tf32.f32 %0, %1;" : "=r"(u) : "f"(x));
    return __uint_as_float(u);
}

__device__ __forceinline__ void mma_tf32(float c[4], const uint32_t a[4], const uint32_t b[2]) {
    asm volatile(
        "mma.sync.aligned.m16n8k8.row.col.f32.tf32.tf32.f32 "
        "{%0,%1,%2,%3}, {%4,%5,%6,%7}, {%8,%9}, {%0,%1,%2,%3};"
        : "+f"(c[0]), "+f"(c[1]), "+f"(c[2]), "+f"(c[3])
        : "r"(a[0]), "r"(a[1]), "r"(a[2]), "r"(a[3]), "r"(b[0]), "r"(b[1]));
}

// ---------------- LN1 + cyclic shift + window partition (warp per token) ----------------
__global__ __launch_bounds__(256) void ln1_gather_k(
    const float* __restrict__ x, const float* __restrict__ g,
    const float* __restrict__ beta, float* __restrict__ out)
{
    int warp = (blockIdx.x * blockDim.x + threadIdx.x) >> 5;
    int lane = threadIdx.x & 31;
    if (warp >= NTOK) return;
    int win = warp >> 6, n = warp & 63;
    int b   = win >> 8;
    int wh  = (win >> 4) & 15;
    int ww  = win & 15;
    int r   = n >> 3, c = n & 7;
    int i = (wh * WIN + r + SHIFT) & 127;
    int j = (ww * WIN + c + SHIFT) & 127;
    const float* src = x + ((size_t)b * (HH*WW_) + (size_t)i * WW_ + j) * CC;

    float v[6];
    float sum = 0.f;
    #pragma unroll
    for (int u = 0; u < 6; ++u) { v[u] = src[lane + u*32]; sum += v[u]; }
    #pragma unroll
    for (int o = 16; o; o >>= 1) sum += __shfl_xor_sync(0xffffffffu, sum, o);
    float mean = sum * (1.f/192.f);
    float var = 0.f;
    #pragma unroll
    for (int u = 0; u < 6; ++u) { float d = v[u]-mean; var += d*d; }
    #pragma unroll
    for (int o = 16; o; o >>= 1) var += __shfl_xor_sync(0xffffffffu, var, o);
    var *= (1.f/192.f);
    float rstd = rsqrtf(var + 1e-5f);
    float* dst = out + (size_t)warp * CC;
    #pragma unroll
    for (int u = 0; u < 6; ++u) {
        int ch = lane + u*32;
        dst[ch] = (v[u]-mean)*rstd*g[ch] + beta[ch];
    }
}

// ---------------- tf32 tensor-core GEMM (128x64 tile, double-buffered) ----------------
// EPI 0: +bias. EPI 3: +bias,+resid with window-reverse row remap.
template<int EPI>
__global__ __launch_bounds__(256) void mma_gemm_k(
    const float* __restrict__ A, const float* __restrict__ B,
    const float* __restrict__ bias, const float* __restrict__ resid,
    float* __restrict__ C, int M, int N, int K)
{
    __shared__ float As[2][128][20];
    __shared__ float Bs[2][64][20];

    const int bm = blockIdx.y * 128;
    const int bn = blockIdx.x * 64;
    const int tid  = threadIdx.x;
    const int lane = tid & 31;
    const int warp = tid >> 5;
    const int wm = warp & 3;
    const int wn = warp >> 2;
    const int qrow = lane >> 2;
    const int qcol = lane & 3;

    const int gr = tid >> 2;
    const int gc = (tid & 3) << 2;
    const float* Ap0 = A + (size_t)(bm + gr)      * K + gc;
    const float* Ap1 = A + (size_t)(bm + gr + 64) * K + gc;
    const float* Bp  = B + (size_t)(bn + gr)      * K + gc;

    float acc[2][4][4];
    #pragma unroll
    for (int i = 0; i < 2; ++i)
        #pragma unroll
        for (int j = 0; j < 4; ++j)
            #pragma unroll
            for (int r = 0; r < 4; ++r) acc[i][j][r] = 0.f;

    float4 ra0 = *(const float4*)(Ap0);
    float4 ra1 = *(const float4*)(Ap1);
    float4 rb  = *(const float4*)(Bp);

    As[0][gr   ][gc+0] = tf32f(ra0.x);
    As[0][gr   ][gc+1] = tf32f(ra0.y);
    As[0][gr   ][gc+2] = tf32f(ra0.z);
    As[0][gr   ][gc+3] = tf32f(ra0.w);
    As[0][gr+64][gc+0] = tf32f(ra1.x);
    As[0][gr+64][gc+1] = tf32f(ra1.y);
    As[0][gr+64][gc+2] = tf32f(ra1.z);
    As[0][gr+64][gc+3] = tf32f(ra1.w);
    Bs[0][gr][gc+0] = tf32f(rb.x);
    Bs[0][gr][gc+1] = tf32f(rb.y);
    Bs[0][gr][gc+2] = tf32f(rb.z);
    Bs[0][gr][gc+3] = tf32f(rb.w);
    __syncthreads();

    int buf = 0;
    for (int k0 = 0; ; k0 += 16) {
        const bool more = (k0 + 16) < K;
        if (more) {
            ra0 = *(const float4*)(Ap0 + k0 + 16);
            ra1 = *(const float4*)(Ap1 + k0 + 16);
            rb  = *(const float4*)(Bp  + k0 + 16);
        }
        #pragma unroll
        for (int ks = 0; ks < 16; ks += 8) {
            uint32_t afr[2][4];
            #pragma unroll
            for (int mt = 0; mt < 2; ++mt) {
                int r = wm*32 + mt*16 + qrow;
                afr[mt][0] = __float_as_uint(As[buf][r  ][ks + qcol    ]);
                afr[mt][1] = __float_as_uint(As[buf][r+8][ks + qcol    ]);
                afr[mt][2] = __float_as_uint(As[buf][r  ][ks + qcol + 4]);
                afr[mt][3] = __float_as_uint(As[buf][r+8][ks + qcol + 4]);
            }
            uint32_t bfr[4][2];
            #pragma unroll
            for (int nt = 0; nt < 4; ++nt) {
                int n = wn*32 + nt*8 + qrow;
                bfr[nt][0] = __float_as_uint(Bs[buf][n][ks + qcol    ]);
                bfr[nt][1] = __float_as_uint(Bs[buf][n][ks + qcol + 4]);
            }
            #pragma unroll
            for (int mt = 0; mt < 2; ++mt)
                #pragma unroll
                for (int nt = 0; nt < 4; ++nt)
                    mma_tf32(acc[mt][nt], afr[mt], bfr[nt]);
        }
        if (!more) break;
        const int ob = buf ^ 1;
        As[ob][gr   ][gc+0] = tf32f(ra0.x);
        As[ob][gr   ][gc+1] = tf32f(ra0.y);
        As[ob][gr   ][gc+2] = tf32f(ra0.z);
        As[ob][gr   ][gc+3] = tf32f(ra0.w);
        As[ob][gr+64][gc+0] = tf32f(ra1.x);
        As[ob][gr+64][gc+1] = tf32f(ra1.y);
        As[ob][gr+64][gc+2] = tf32f(ra1.z);
        As[ob][gr+64][gc+3] = tf32f(ra1.w);
        Bs[ob][gr][gc+0] = tf32f(rb.x);
        Bs[ob][gr][gc+1] = tf32f(rb.y);
        Bs[ob][gr][gc+2] = tf32f(rb.z);
        Bs[ob][gr][gc+3] = tf32f(rb.w);
        __syncthreads();
        buf = ob;
    }

    #pragma unroll
    for (int mt = 0; mt < 2; ++mt) {
        #pragma unroll
        for (int half = 0; half < 2; ++half) {
            int row = bm + wm*32 + mt*16 + qrow + half*8;
            size_t orow;
            if (EPI == 3) {
                int win = row >> 6, nn = row & 63;
                int b   = win >> 8;
                int wh  = (win >> 4) & 15;
                int ww  = win & 15;
                int rr  = nn >> 3, cc = nn & 7;
                int i = (wh*WIN + rr + SHIFT) & 127;
                int j = (ww*WIN + cc + SHIFT) & 127;
                orow = (size_t)b * (HH*WW_) + (size_t)i * WW_ + j;
            } else {
                orow = (size_t)row;
            }
            #pragma unroll
            for (int nt = 0; nt < 4; ++nt) {
                int col0 = bn + wn*32 + nt*8 + qcol*2;
                #pragma unroll
                for (int e = 0; e < 2; ++e) {
                    int col = col0 + e;
                    float v = acc[mt][nt][half*2 + e] + bias[col];
                    if (EPI == 3) v += resid[orow * N + col];
                    C[orow * N + col] = v;
                }
            }
        }
    }
}

// ---------------- fused LN2 + MLP1 + GELU + MLP2 + residual ----------------
// One block = 64 token rows. A (LN2'd, tf32) resident in smem; hidden chunk (64 wide)
// bounced through smem; C[64x192] accumulated in registers; weights streamed from L2.
__global__ __launch_bounds__(256, 2) void fused_mlp_k(
    const float* __restrict__ x1, const float* __restrict__ n2g,
    const float* __restrict__ n2b, const float* __restrict__ w1,
    const float* __restrict__ b1, const float* __restrict__ w2,
    const float* __restrict__ b2, float* __restrict__ out)
{
    extern __shared__ float smem[];
    float* As = smem;                 // [64][196]
    float* Hs = As + 64*196;          // [64][68]
    float* Ws = Hs + 64*68;           // [2][192][20]

    const int row0 = blockIdx.x * 64;
    const int tid  = threadIdx.x;
    const int lane = tid & 31;
    const int warp = tid >> 5;
    const int qrow = lane >> 2;
    const int qcol = lane & 3;
    const int wm = warp & 1;          // 2 M-halves of 32
    const int wn = warp >> 1;         // 4 N-groups

    // ---- LN2 staging: warp w handles rows w*8..w*8+7 ----
    #pragma unroll
    for (int rr = 0; rr < 8; ++rr) {
        int row = warp*8 + rr;
        const float* src = x1 + (size_t)(row0 + row) * CC;
        float v[6];
        float s = 0.f;
        #pragma unroll
        for (int u = 0; u < 6; ++u) { v[u] = src[lane + u*32]; s += v[u]; }
        #pragma unroll
        for (int o = 16; o; o >>= 1) s += __shfl_xor_sync(0xffffffffu, s, o);
        float mean = s * (1.f/192.f);
        float var = 0.f;
        #pragma unroll
        for (int u = 0; u < 6; ++u) { float d = v[u]-mean; var += d*d; }
        #pragma unroll
        for (int o = 16; o; o >>= 1) var += __shfl_xor_sync(0xffffffffu, var, o);
        var *= (1.f/192.f);
        float rstd = rsqrtf(var + 1e-5f);
        #pragma unroll
        for (int u = 0; u < 6; ++u) {
            int ch = lane + u*32;
            As[row*196 + ch] = tf32f((v[u]-mean)*rstd*n2g[ch] + n2b[ch]);
        }
    }
    __syncthreads();

    float accC[2][6][4];
    #pragma unroll
    for (int i = 0; i < 2; ++i)
        #pragma unroll
        for (int j = 0; j < 6; ++j)
            #pragma unroll
            for (int r = 0; r < 4; ++r) accC[i][j][r] = 0.f;

    const int r1 = tid >> 2;            // 0..63  (W1 staging row)
    const int q1 = (tid & 3) << 2;      // 0,4,8,12

    for (int hc = 0; hc < 12; ++hc) {
        // ======== GEMM1: H[64x64] = As @ W1[hc*64.. , :]^T ========
        float accH[2][2][4];
        #pragma unroll
        for (int i = 0; i < 2; ++i)
            #pragma unroll
            for (int j = 0; j < 2; ++j)
                #pragma unroll
                for (int r = 0; r < 4; ++r) accH[i][j][r] = 0.f;

        const float* W1p = w1 + (size_t)(hc*64 + r1) * CC + q1;
        float4 wreg = *(const float4*)(W1p);
        {
            float* d = Ws + 0*192*20 + r1*20 + q1;
            d[0] = tf32f(wreg.x); d[1] = tf32f(wreg.y);
            d[2] = tf32f(wreg.z); d[3] = tf32f(wreg.w);
        }
        __syncthreads();
        int buf = 0;
        for (int k0 = 0; ; k0 += 16) {
            const bool more = (k0 + 16) < CC;
            if (more) wreg = *(const float4*)(W1p + k0 + 16);
            #pragma unroll
            for (int ks = 0; ks < 16; ks += 8) {
                uint32_t afr[2][4];
                #pragma unroll
                for (int mt = 0; mt < 2; ++mt) {
                    int r = wm*32 + mt*16 + qrow;
                    int k = k0 + ks + qcol;
                    afr[mt][0] = __float_as_uint(As[r*196     + k]);
                    afr[mt][1] = __float_as_uint(As[(r+8)*196 + k]);
                    afr[mt][2] = __float_as_uint(As[r*196     + k + 4]);
                    afr[mt][3] = __float_as_uint(As[(r+8)*196 + k + 4]);
                }
                uint32_t bfr[2][2];
                #pragma unroll
                for (int nt = 0; nt < 2; ++nt) {
                    int n = wn*16 + nt*8 + qrow;
                    bfr[nt][0] = __float_as_uint(Ws[buf*192*20 + n*20 + ks + qcol]);
                    bfr[nt][1] = __float_as_uint(Ws[buf*192*20 + n*20 + ks + qcol + 4]);
                }
                #pragma unroll
                for (int mt = 0; mt < 2; ++mt)
                    #pragma unroll
                    for (int nt = 0; nt < 2; ++nt)
                        mma_tf32(accH[mt][nt], afr[mt], bfr[nt]);
            }
            if (!more) break;
            const int ob = buf ^ 1;
            float* d = Ws + ob*192*20 + r1*20 + q1;
            d[0] = tf32f(wreg.x); d[1] = tf32f(wreg.y);
            d[2] = tf32f(wreg.z); d[3] = tf32f(wreg.w);
            __syncthreads();
            buf = ob;
        }
        __syncthreads();   // GEMM1 reads of Ws done before restaging

        // ---- bias + GELU -> Hs (tf32) ----
        #pragma unroll
        for (int mt = 0; mt < 2; ++mt) {
            #pragma unroll
            for (int nt = 0; nt < 2; ++nt) {
                #pragma unroll
                for (int half = 0; half < 2; ++half) {
                    int row = wm*32 + mt*16 + qrow + half*8;
                    #pragma unroll
                    for (int e = 0; e < 2; ++e) {
                        int col = wn*16 + nt*8 + qcol*2 + e;
                        float v = accH[mt][nt][half*2 + e] + b1[hc*64 + col];
                        v = 0.5f * v * (1.0f + erff(v * 0.70710678118654752f));
                        Hs[row*68 + col] = tf32f(v);
                    }
                }
            }
        }
        __syncthreads();

        // ======== GEMM2: accC += Hs @ W2[:, hc*64..]^T  (K=64) ========
        float4 w2reg[3];
        #pragma unroll
        for (int i = 0; i < 3; ++i) {
            int idx = i*256 + tid;
            int r2 = idx >> 2, q2 = (idx & 3) << 2;
            w2reg[i] = *(const float4*)(w2 + (size_t)r2 * (4*CC) + hc*64 + q2);
        }
        #pragma unroll
        for (int i = 0; i < 3; ++i) {
            int idx = i*256 + tid;
            int r2 = idx >> 2, q2 = (idx & 3) << 2;
            float* d = Ws + 0*192*20 + r2*20 + q2;
            d[0] = tf32f(w2reg[i].x); d[1] = tf32f(w2reg[i].y);
            d[2] = tf32f(w2reg[i].z); d[3] = tf32f(w2reg[i].w);
        }
        __syncthreads();
        buf = 0;
        for (int k2 = 0; ; k2 += 16) {
            const bool more = (k2 + 16) < 64;
            if (more) {
                #pragma unroll
                for (int i = 0; i < 3; ++i) {
                    int idx = i*256 + tid;
                    int r2 = idx >> 2, q2 = (idx & 3) << 2;
                    w2reg[i] = *(const float4*)(w2 + (size_t)r2 * (4*CC) + hc*64 + k2 + 16 + q2);
                }
            }
            #pragma unroll
            for (int ks = 0; ks < 16; ks += 8) {
                uint32_t afr[2][4];
                #pragma unroll
                for (int mt = 0; mt < 2; ++mt) {
                    int r = wm*32 + mt*16 + qrow;
                    int k = k2 + ks + qcol;
                    afr[mt][0] = __float_as_uint(Hs[r*68     + k]);
                    afr[mt][1] = __float_as_uint(Hs[(r+8)*68 + k]);
                    afr[mt][2] = __float_as_uint(Hs[r*68     + k + 4]);
                    afr[mt][3] = __float_as_uint(Hs[(r+8)*68 + k + 4]);
                }
                uint32_t bfr[6][2];
                #pragma unroll
                for (int nt = 0; nt < 6; ++nt) {
                    int n = wn*48 + nt*8 + qrow;
                    bfr[nt][0] = __float_as_uint(Ws[buf*192*20 + n*20 + ks + qcol]);
                    bfr[nt][1] = __float_as_uint(Ws[buf*192*20 + n*20 + ks + qcol + 4]);
                }
                #pragma unroll
                for (int mt = 0; mt < 2; ++mt)
                    #pragma unroll
                    for (int nt = 0; nt < 6; ++nt)
                        mma_tf32(accC[mt][nt], afr[mt], bfr[nt]);
            }
            if (!more) break;
            const int ob = buf ^ 1;
            #pragma unroll
            for (int i = 0; i < 3; ++i) {
                int idx = i*256 + tid;
                int r2 = idx >> 2, q2 = (idx & 3) << 2;
                float* d = Ws + ob*192*20 + r2*20 + q2;
                d[0] = tf32f(w2reg[i].x); d[1] = tf32f(w2reg[i].y);
                d[2] = tf32f(w2reg[i].z); d[3] = tf32f(w2reg[i].w);
            }
            __syncthreads();
            buf = ob;
        }
        __syncthreads();   // before next chunk restages Ws / rewrites Hs
    }

    // ---- epilogue: +b2 +x1 residual -> out ----
    #pragma unroll
    for (int mt = 0; mt < 2; ++mt) {
        #pragma unroll
        for (int half = 0; half < 2; ++half) {
            int row = row0 + wm*32 + mt*16 + qrow + half*8;
            #pragma unroll
            for (int nt = 0; nt < 6; ++nt) {
                #pragma unroll
                for (int e = 0; e < 2; ++e) {
                    int col = wn*48 + nt*8 + qcol*2 + e;
                    float v = accC[mt][nt][half*2 + e] + b2[col]
                            + x1[(size_t)row * CC + col];
                    out[(size_t)row * CC + col] = v;
                }
            }
        }
    }
}

// ---------------- windowed attention (R3-validated) ----------------
__global__ __launch_bounds__(64) void attn_k(
    const float* __restrict__ qkv, float* __restrict__ attno)
{
    const int win = blockIdx.x / HEADS;
    const int h   = blockIdx.x % HEADS;
    const int t   = threadIdx.x;
    __shared__ float4 ks4[NN][9];
    __shared__ float4 vs4[NN][9];

    const float4* base = (const float4*)(qkv + (size_t)(win * NN + t) * (3*CC) + h * HD);

    float4 q4[8];
    float nq = 0.f;
    #pragma unroll
    for (int i = 0; i < 8; ++i) {
        q4[i] = base[i];
        nq += q4[i].x*q4[i].x + q4[i].y*q4[i].y + q4[i].z*q4[i].z + q4[i].w*q4[i].w;
    }
    const float scale = 0.17677669529663687f;
    float invq = scale / fmaxf(sqrtf(nq), 1e-12f);
    #pragma unroll
    for (int i = 0; i < 8; ++i) {
        q4[i].x *= invq; q4[i].y *= invq; q4[i].z *= invq; q4[i].w *= invq;
    }

    {
        float4 kk[8];
        float nk = 0.f;
        #pragma unroll
        for (int i = 0; i < 8; ++i) {
            kk[i] = base[(CC/4) + i];
            nk += kk[i].x*kk[i].x + kk[i].y*kk[i].y + kk[i].z*kk[i].z + kk[i].w*kk[i].w;
        }
        float invk = 1.f / fmaxf(sqrtf(nk), 1e-12f);
        #pragma unroll
        for (int i = 0; i < 8; ++i) {
            float4 o;
            o.x = kk[i].x*invk; o.y = kk[i].y*invk; o.z = kk[i].z*invk; o.w = kk[i].w*invk;
            ks4[t][i] = o;
        }
        #pragma unroll
        for (int i = 0; i < 8; ++i) vs4[t][i] = base[(2*CC/4) + i];
    }
    __syncthreads();

    float sum = 0.f;
    float4 o4[8];
    #pragma unroll
    for (int i = 0; i < 8; ++i) { o4[i].x = 0.f; o4[i].y = 0.f; o4[i].z = 0.f; o4[i].w = 0.f; }

    #pragma unroll 8
    for (int m = 0; m < NN; ++m) {
        float d0 = 0.f, d1 = 0.f, d2 = 0.f, d3 = 0.f;
        #pragma unroll
        for (int i = 0; i < 8; ++i) {
            float4 kk = ks4[m][i];
            d0 += q4[i].x * kk.x;
            d1 += q4[i].y * kk.y;
            d2 += q4[i].z * kk.z;
            d3 += q4[i].w * kk.w;
        }
        float xx = (d0 + d1) + (d2 + d3);
        float e = 8.3333333e-3f;
        e = e * xx + 4.1666667e-2f;
        e = e * xx + 1.6666667e-1f;
        e = e * xx + 0.5f;
        e = e * xx + 1.0f;
        e = e * xx + 1.0f;
        sum += e;
        #pragma unroll
        for (int i = 0; i < 8; ++i) {
            float4 vv = vs4[m][i];
            o4[i].x += e * vv.x;
            o4[i].y += e * vv.y;
            o4[i].z += e * vv.z;
            o4[i].w += e * vv.w;
        }
    }
    float rs = 1.f / sum;
    float4* dst = (float4*)(attno + (size_t)(win * NN + t) * CC + h * HD);
    #pragma unroll
    for (int i = 0; i < 8; ++i) {
        float4 o;
        o.x = o4[i].x * rs; o.y = o4[i].y * rs; o.z = o4[i].z * rs; o.w = o4[i].w * rs;
        dst[i] = o;
    }
}

// ---------------- host launcher ----------------
extern "C" void kernel_launch(void* const* d_in, const int* in_sizes, int n_in,
                              void* d_out, int out_size)
{
    const float* x      = (const float*)d_in[0];
    const float* qkv_w  = (const float*)d_in[1];
    const float* qkv_b  = (const float*)d_in[2];
    const float* proj_w = (const float*)d_in[3];
    const float* proj_b = (const float*)d_in[4];
    const float* n1_g   = (const float*)d_in[5];
    const float* n1_b   = (const float*)d_in[6];
    const float* n2_g   = (const float*)d_in[7];
    const float* n2_b   = (const float*)d_in[8];
    const float* w1     = (const float*)d_in[9];
    const float* b1     = (const float*)d_in[10];
    const float* w2     = (const float*)d_in[11];
    const float* b2     = (const float*)d_in[12];
    float* out = (float*)d_out;

    float *hwin, *qkv, *attno, *x1;
    cudaGetSymbolAddress((void**)&hwin,  g_hwin);
    cudaGetSymbolAddress((void**)&qkv,   g_qkv);
    cudaGetSymbolAddress((void**)&attno, g_attno);
    cudaGetSymbolAddress((void**)&x1,    g_x1);

    const int FUSED_SMEM = (64*196 + 64*68 + 2*192*20) * 4;   // 98304 B
    cudaFuncSetAttribute(fused_mlp_k, cudaFuncAttributeMaxDynamicSharedMemorySize, FUSED_SMEM);

    // 1) LN1 + shift + window gather
    ln1_gather_k<<<NTOK/8, 256>>>(x, n1_g, n1_b, hwin);

    // 2) QKV GEMM
    mma_gemm_k<0><<<dim3((3*CC)/64, NTOK/128), 256>>>(hwin, qkv_w, qkv_b, nullptr, qkv,
                                                      NTOK, 3*CC, CC);

    // 3) attention per (window, head)
    attn_k<<<NWIN * HEADS, 64>>>(qkv, attno);

    // 4) proj GEMM + window reverse + residual -> x1 (token order)
    mma_gemm_k<3><<<dim3(CC/64, NTOK/128), 256>>>(attno, proj_w, proj_b, x, x1,
                                                  NTOK, CC, CC);

    // 5) fused LN2 + MLP1 + GELU + MLP2 + residual -> out
    fused_mlp_k<<<NTOK/64, 256, FUSED_SMEM>>>(x1, n2_g, n2_b, w1, b1, w2, b2, out);
}

// round 7
// speedup vs baseline: 2.9175x; 1.0973x over previous
#include <cuda_runtime.h>
#include <cuda_bf16.h>
#include <cstdint>
#include <cstdio>

// ---------------- problem constants ----------------
#define BIMG   16
#define HH     128
#define WW_    128
#define CC     192
#define HEADS  6
#define HD     32
#define WIN    8
#define SHIFT  4
#define NTOK   (BIMG * HH * WW_)              // 262144 tokens
#define NWIN   (BIMG * (HH/WIN) * (WW_/WIN))  // 4096 windows
#define NN     (WIN * WIN)                    // 64 tokens per window

// ---------------- scratch ----------------
__device__ float g_hwin [ (size_t)NTOK * CC ];
__device__ float g_qkv  [ (size_t)NTOK * 3 * CC ];
__device__ float g_attno[ (size_t)NTOK * CC ];
__device__ float g_x1   [ (size_t)NTOK * CC ];

// ---------------- helpers ----------------
__device__ __forceinline__ float tf32f(float x) {
    uint32_t u;
    asm("cvt.rna.tf32.f32 %0, %1;" : "=r"(u) : "f"(x));
    return __uint_as_float(u);
}

__device__ __forceinline__ void mma_tf32(float c[4], const uint32_t a[4], const uint32_t b[2]) {
    asm volatile(
        "mma.sync.aligned.m16n8k8.row.col.f32.tf32.tf32.f32 "
        "{%0,%1,%2,%3}, {%4,%5,%6,%7}, {%8,%9}, {%0,%1,%2,%3};"
        : "+f"(c[0]), "+f"(c[1]), "+f"(c[2]), "+f"(c[3])
        : "r"(a[0]), "r"(a[1]), "r"(a[2]), "r"(a[3]), "r"(b[0]), "r"(b[1]));
}

// exp(x) for |x| <= 0.1768 (l2-normed logits): degree-5 Taylor, rel err < 5e-9
__device__ __forceinline__ float exp_small(float x) {
    float e = 8.3333333e-3f;
    e = e * x + 4.1666667e-2f;
    e = e * x + 1.6666667e-1f;
    e = e * x + 0.5f;
    e = e * x + 1.0f;
    e = e * x + 1.0f;
    return e;
}

// ---------------- LN1 + cyclic shift + window partition (warp per token) ----------------
__global__ __launch_bounds__(256) void ln1_gather_k(
    const float* __restrict__ x, const float* __restrict__ g,
    const float* __restrict__ beta, float* __restrict__ out)
{
    int warp = (blockIdx.x * blockDim.x + threadIdx.x) >> 5;
    int lane = threadIdx.x & 31;
    if (warp >= NTOK) return;
    int win = warp >> 6, n = warp & 63;
    int b   = win >> 8;
    int wh  = (win >> 4) & 15;
    int ww  = win & 15;
    int r   = n >> 3, c = n & 7;
    int i = (wh * WIN + r + SHIFT) & 127;
    int j = (ww * WIN + c + SHIFT) & 127;
    const float* src = x + ((size_t)b * (HH*WW_) + (size_t)i * WW_ + j) * CC;

    float v[6];
    float sum = 0.f;
    #pragma unroll
    for (int u = 0; u < 6; ++u) { v[u] = src[lane + u*32]; sum += v[u]; }
    #pragma unroll
    for (int o = 16; o; o >>= 1) sum += __shfl_xor_sync(0xffffffffu, sum, o);
    float mean = sum * (1.f/192.f);
    float var = 0.f;
    #pragma unroll
    for (int u = 0; u < 6; ++u) { float d = v[u]-mean; var += d*d; }
    #pragma unroll
    for (int o = 16; o; o >>= 1) var += __shfl_xor_sync(0xffffffffu, var, o);
    var *= (1.f/192.f);
    float rstd = rsqrtf(var + 1e-5f);
    float* dst = out + (size_t)warp * CC;
    #pragma unroll
    for (int u = 0; u < 6; ++u) {
        int ch = lane + u*32;
        dst[ch] = (v[u]-mean)*rstd*g[ch] + beta[ch];
    }
}

// ---------------- tf32 tensor-core GEMM (128x64 tile, double-buffered) ----------------
// EPI 0: +bias. EPI 3: +bias,+resid with window-reverse row remap.
template<int EPI>
__global__ __launch_bounds__(256) void mma_gemm_k(
    const float* __restrict__ A, const float* __restrict__ B,
    const float* __restrict__ bias, const float* __restrict__ resid,
    float* __restrict__ C, int M, int N, int K)
{
    __shared__ float As[2][128][20];
    __shared__ float Bs[2][64][20];

    const int bm = blockIdx.y * 128;
    const int bn = blockIdx.x * 64;
    const int tid  = threadIdx.x;
    const int lane = tid & 31;
    const int warp = tid >> 5;
    const int wm = warp & 3;
    const int wn = warp >> 2;
    const int qrow = lane >> 2;
    const int qcol = lane & 3;

    const int gr = tid >> 2;
    const int gc = (tid & 3) << 2;
    const float* Ap0 = A + (size_t)(bm + gr)      * K + gc;
    const float* Ap1 = A + (size_t)(bm + gr + 64) * K + gc;
    const float* Bp  = B + (size_t)(bn + gr)      * K + gc;

    float acc[2][4][4];
    #pragma unroll
    for (int i = 0; i < 2; ++i)
        #pragma unroll
        for (int j = 0; j < 4; ++j)
            #pragma unroll
            for (int r = 0; r < 4; ++r) acc[i][j][r] = 0.f;

    float4 ra0 = *(const float4*)(Ap0);
    float4 ra1 = *(const float4*)(Ap1);
    float4 rb  = *(const float4*)(Bp);

    As[0][gr   ][gc+0] = tf32f(ra0.x);
    As[0][gr   ][gc+1] = tf32f(ra0.y);
    As[0][gr   ][gc+2] = tf32f(ra0.z);
    As[0][gr   ][gc+3] = tf32f(ra0.w);
    As[0][gr+64][gc+0] = tf32f(ra1.x);
    As[0][gr+64][gc+1] = tf32f(ra1.y);
    As[0][gr+64][gc+2] = tf32f(ra1.z);
    As[0][gr+64][gc+3] = tf32f(ra1.w);
    Bs[0][gr][gc+0] = tf32f(rb.x);
    Bs[0][gr][gc+1] = tf32f(rb.y);
    Bs[0][gr][gc+2] = tf32f(rb.z);
    Bs[0][gr][gc+3] = tf32f(rb.w);
    __syncthreads();

    int buf = 0;
    for (int k0 = 0; ; k0 += 16) {
        const bool more = (k0 + 16) < K;
        if (more) {
            ra0 = *(const float4*)(Ap0 + k0 + 16);
            ra1 = *(const float4*)(Ap1 + k0 + 16);
            rb  = *(const float4*)(Bp  + k0 + 16);
        }
        #pragma unroll
        for (int ks = 0; ks < 16; ks += 8) {
            uint32_t afr[2][4];
            #pragma unroll
            for (int mt = 0; mt < 2; ++mt) {
                int r = wm*32 + mt*16 + qrow;
                afr[mt][0] = __float_as_uint(As[buf][r  ][ks + qcol    ]);
                afr[mt][1] = __float_as_uint(As[buf][r+8][ks + qcol    ]);
                afr[mt][2] = __float_as_uint(As[buf][r  ][ks + qcol + 4]);
                afr[mt][3] = __float_as_uint(As[buf][r+8][ks + qcol + 4]);
            }
            uint32_t bfr[4][2];
            #pragma unroll
            for (int nt = 0; nt < 4; ++nt) {
                int n = wn*32 + nt*8 + qrow;
                bfr[nt][0] = __float_as_uint(Bs[buf][n][ks + qcol    ]);
                bfr[nt][1] = __float_as_uint(Bs[buf][n][ks + qcol + 4]);
            }
            #pragma unroll
            for (int mt = 0; mt < 2; ++mt)
                #pragma unroll
                for (int nt = 0; nt < 4; ++nt)
                    mma_tf32(acc[mt][nt], afr[mt], bfr[nt]);
        }
        if (!more) break;
        const int ob = buf ^ 1;
        As[ob][gr   ][gc+0] = tf32f(ra0.x);
        As[ob][gr   ][gc+1] = tf32f(ra0.y);
        As[ob][gr   ][gc+2] = tf32f(ra0.z);
        As[ob][gr   ][gc+3] = tf32f(ra0.w);
        As[ob][gr+64][gc+0] = tf32f(ra1.x);
        As[ob][gr+64][gc+1] = tf32f(ra1.y);
        As[ob][gr+64][gc+2] = tf32f(ra1.z);
        As[ob][gr+64][gc+3] = tf32f(ra1.w);
        Bs[ob][gr][gc+0] = tf32f(rb.x);
        Bs[ob][gr][gc+1] = tf32f(rb.y);
        Bs[ob][gr][gc+2] = tf32f(rb.z);
        Bs[ob][gr][gc+3] = tf32f(rb.w);
        __syncthreads();
        buf = ob;
    }

    #pragma unroll
    for (int mt = 0; mt < 2; ++mt) {
        #pragma unroll
        for (int half = 0; half < 2; ++half) {
            int row = bm + wm*32 + mt*16 + qrow + half*8;
            size_t orow;
            if (EPI == 3) {
                int win = row >> 6, nn = row & 63;
                int b   = win >> 8;
                int wh  = (win >> 4) & 15;
                int ww  = win & 15;
                int rr  = nn >> 3, cc = nn & 7;
                int i = (wh*WIN + rr + SHIFT) & 127;
                int j = (ww*WIN + cc + SHIFT) & 127;
                orow = (size_t)b * (HH*WW_) + (size_t)i * WW_ + j;
            } else {
                orow = (size_t)row;
            }
            #pragma unroll
            for (int nt = 0; nt < 4; ++nt) {
                int col0 = bn + wn*32 + nt*8 + qcol*2;
                #pragma unroll
                for (int e = 0; e < 2; ++e) {
                    int col = col0 + e;
                    float v = acc[mt][nt][half*2 + e] + bias[col];
                    if (EPI == 3) v += resid[orow * N + col];
                    C[orow * N + col] = v;
                }
            }
        }
    }
}

// ---------------- tensor-core windowed attention: one block per window ----------------
// 256 threads = 8 warps (4 m-tiles x 2 n-halves). Heads sequential.
// Logits bounded by +-0.1768 (l2-normed q,k): no max-subtract, clip is a no-op.
__global__ __launch_bounds__(256) void attn_mma_k(
    const float* __restrict__ qkv, float* __restrict__ attno)
{
    __shared__ float Qs[64][36];     // [token][dim], pad 36 -> conflict-free frags
    __shared__ float Ks[64][36];
    __shared__ float Vs[32][68];     // transposed: [dim][token], pad 68
    __shared__ float Ps[64][68];     // exp'd scores [query][key]
    __shared__ float Ssum[2][64];    // per-n-half partial row sums

    const int win  = blockIdx.x;
    const int tid  = threadIdx.x;
    const int lane = tid & 31;
    const int warp = tid >> 5;
    const int qrow = lane >> 2;      // 0..7
    const int qcol = lane & 3;       // 0..3
    const int wm   = warp >> 1;      // 0..3 (m16 tile)
    const int wn   = warp & 1;       // 0..1 (n-half)
    const int sr   = tid >> 2;       // staging row 0..63
    const int sq   = tid & 3;        // staging quarter

    const float scale = 0.17677669529663687f;   // 1/sqrt(32)

    for (int h = 0; h < HEADS; ++h) {
        // ---- stage Q (l2norm*scale), K (l2norm), V^T ----
        {
            const float* rowp = qkv + (size_t)(win*NN + sr)*(3*CC) + h*HD + sq*8;
            float4 qa = *(const float4*)(rowp);
            float4 qb = *(const float4*)(rowp + 4);
            float ss = qa.x*qa.x + qa.y*qa.y + qa.z*qa.z + qa.w*qa.w
                     + qb.x*qb.x + qb.y*qb.y + qb.z*qb.z + qb.w*qb.w;
            ss += __shfl_xor_sync(0xffffffffu, ss, 1);
            ss += __shfl_xor_sync(0xffffffffu, ss, 2);
            float invq = scale / fmaxf(sqrtf(ss), 1e-12f);
            Qs[sr][sq*8+0] = tf32f(qa.x*invq); Qs[sr][sq*8+1] = tf32f(qa.y*invq);
            Qs[sr][sq*8+2] = tf32f(qa.z*invq); Qs[sr][sq*8+3] = tf32f(qa.w*invq);
            Qs[sr][sq*8+4] = tf32f(qb.x*invq); Qs[sr][sq*8+5] = tf32f(qb.y*invq);
            Qs[sr][sq*8+6] = tf32f(qb.z*invq); Qs[sr][sq*8+7] = tf32f(qb.w*invq);

            float4 ka = *(const float4*)(rowp + CC);
            float4 kb = *(const float4*)(rowp + CC + 4);
            float sk = ka.x*ka.x + ka.y*ka.y + ka.z*ka.z + ka.w*ka.w
                     + kb.x*kb.x + kb.y*kb.y + kb.z*kb.z + kb.w*kb.w;
            sk += __shfl_xor_sync(0xffffffffu, sk, 1);
            sk += __shfl_xor_sync(0xffffffffu, sk, 2);
            float invk = 1.f / fmaxf(sqrtf(sk), 1e-12f);
            Ks[sr][sq*8+0] = tf32f(ka.x*invk); Ks[sr][sq*8+1] = tf32f(ka.y*invk);
            Ks[sr][sq*8+2] = tf32f(ka.z*invk); Ks[sr][sq*8+3] = tf32f(ka.w*invk);
            Ks[sr][sq*8+4] = tf32f(kb.x*invk); Ks[sr][sq*8+5] = tf32f(kb.y*invk);
            Ks[sr][sq*8+6] = tf32f(kb.z*invk); Ks[sr][sq*8+7] = tf32f(kb.w*invk);

            float4 va = *(const float4*)(rowp + 2*CC);
            float4 vb = *(const float4*)(rowp + 2*CC + 4);
            Vs[sq*8+0][sr] = tf32f(va.x); Vs[sq*8+1][sr] = tf32f(va.y);
            Vs[sq*8+2][sr] = tf32f(va.z); Vs[sq*8+3][sr] = tf32f(va.w);
            Vs[sq*8+4][sr] = tf32f(vb.x); Vs[sq*8+5][sr] = tf32f(vb.y);
            Vs[sq*8+6][sr] = tf32f(vb.z); Vs[sq*8+7][sr] = tf32f(vb.w);
        }
        __syncthreads();

        // ---- S = Q @ K^T : warp tile m16 x n32 (4 n8 tiles), K=32 ----
        float c[4][4];
        #pragma unroll
        for (int nt = 0; nt < 4; ++nt)
            #pragma unroll
            for (int i = 0; i < 4; ++i) c[nt][i] = 0.f;
        #pragma unroll
        for (int ks = 0; ks < 32; ks += 8) {
            uint32_t afr[4];
            int r = wm*16 + qrow;
            afr[0] = __float_as_uint(Qs[r  ][ks + qcol    ]);
            afr[1] = __float_as_uint(Qs[r+8][ks + qcol    ]);
            afr[2] = __float_as_uint(Qs[r  ][ks + qcol + 4]);
            afr[3] = __float_as_uint(Qs[r+8][ks + qcol + 4]);
            #pragma unroll
            for (int nt = 0; nt < 4; ++nt) {
                uint32_t bfr[2];
                int n = wn*32 + nt*8 + qrow;
                bfr[0] = __float_as_uint(Ks[n][ks + qcol    ]);
                bfr[1] = __float_as_uint(Ks[n][ks + qcol + 4]);
                mma_tf32(c[nt], afr, bfr);
            }
        }

        // ---- exp + partial row sums + P -> smem ----
        float s0 = 0.f, s1 = 0.f;
        #pragma unroll
        for (int nt = 0; nt < 4; ++nt) {
            c[nt][0] = exp_small(c[nt][0]);
            c[nt][1] = exp_small(c[nt][1]);
            c[nt][2] = exp_small(c[nt][2]);
            c[nt][3] = exp_small(c[nt][3]);
            s0 += c[nt][0] + c[nt][1];
            s1 += c[nt][2] + c[nt][3];
        }
        s0 += __shfl_xor_sync(0xffffffffu, s0, 1);
        s0 += __shfl_xor_sync(0xffffffffu, s0, 2);
        s1 += __shfl_xor_sync(0xffffffffu, s1, 1);
        s1 += __shfl_xor_sync(0xffffffffu, s1, 2);
        if (qcol == 0) {
            Ssum[wn][wm*16 + qrow    ] = s0;
            Ssum[wn][wm*16 + qrow + 8] = s1;
        }
        #pragma unroll
        for (int nt = 0; nt < 4; ++nt) {
            int col = wn*32 + nt*8 + 2*qcol;
            float2 lo = make_float2(tf32f(c[nt][0]), tf32f(c[nt][1]));
            float2 hi = make_float2(tf32f(c[nt][2]), tf32f(c[nt][3]));
            *(float2*)&Ps[wm*16 + qrow    ][col] = lo;
            *(float2*)&Ps[wm*16 + qrow + 8][col] = hi;
        }
        __syncthreads();

        // ---- O = P @ V : warp tile m16 x n16 (2 n8 tiles), K=64 ----
        float o[2][4];
        #pragma unroll
        for (int nt = 0; nt < 2; ++nt)
            #pragma unroll
            for (int i = 0; i < 4; ++i) o[nt][i] = 0.f;
        #pragma unroll
        for (int ks = 0; ks < 64; ks += 8) {
            uint32_t afr[4];
            int r = wm*16 + qrow;
            afr[0] = __float_as_uint(Ps[r  ][ks + qcol    ]);
            afr[1] = __float_as_uint(Ps[r+8][ks + qcol    ]);
            afr[2] = __float_as_uint(Ps[r  ][ks + qcol + 4]);
            afr[3] = __float_as_uint(Ps[r+8][ks + qcol + 4]);
            #pragma unroll
            for (int nt = 0; nt < 2; ++nt) {
                uint32_t bfr[2];
                int n = wn*16 + nt*8 + qrow;
                bfr[0] = __float_as_uint(Vs[n][ks + qcol    ]);
                bfr[1] = __float_as_uint(Vs[n][ks + qcol + 4]);
                mma_tf32(o[nt], afr, bfr);
            }
        }

        // ---- normalize + write ----
        int row0 = wm*16 + qrow;
        float rs0 = 1.f / (Ssum[0][row0    ] + Ssum[1][row0    ]);
        float rs1 = 1.f / (Ssum[0][row0 + 8] + Ssum[1][row0 + 8]);
        float* dst = attno + (size_t)(win*NN) * CC + h*HD;
        #pragma unroll
        for (int nt = 0; nt < 2; ++nt) {
            int col = wn*16 + nt*8 + 2*qcol;
            float2 lo = make_float2(o[nt][0]*rs0, o[nt][1]*rs0);
            float2 hi = make_float2(o[nt][2]*rs1, o[nt][3]*rs1);
            *(float2*)&dst[(size_t)(row0    ) * CC + col] = lo;
            *(float2*)&dst[(size_t)(row0 + 8) * CC + col] = hi;
        }
        __syncthreads();   // protect smem before next head restages
    }
}

// ---------------- fused LN2 + MLP1 + GELU + MLP2 + residual ----------------
__global__ __launch_bounds__(256, 2) void fused_mlp_k(
    const float* __restrict__ x1, const float* __restrict__ n2g,
    const float* __restrict__ n2b, const float* __restrict__ w1,
    const float* __restrict__ b1, const float* __restrict__ w2,
    const float* __restrict__ b2, float* __restrict__ out)
{
    extern __shared__ float smem[];
    float* As = smem;                 // [64][196]
    float* Hs = As + 64*196;          // [64][68]
    float* Ws = Hs + 64*68;           // [2][192][20]

    const int row0 = blockIdx.x * 64;
    const int tid  = threadIdx.x;
    const int lane = tid & 31;
    const int warp = tid >> 5;
    const int qrow = lane >> 2;
    const int qcol = lane & 3;
    const int wm = warp & 1;
    const int wn = warp >> 1;

    #pragma unroll
    for (int rr = 0; rr < 8; ++rr) {
        int row = warp*8 + rr;
        const float* src = x1 + (size_t)(row0 + row) * CC;
        float v[6];
        float s = 0.f;
        #pragma unroll
        for (int u = 0; u < 6; ++u) { v[u] = src[lane + u*32]; s += v[u]; }
        #pragma unroll
        for (int o = 16; o; o >>= 1) s += __shfl_xor_sync(0xffffffffu, s, o);
        float mean = s * (1.f/192.f);
        float var = 0.f;
        #pragma unroll
        for (int u = 0; u < 6; ++u) { float d = v[u]-mean; var += d*d; }
        #pragma unroll
        for (int o = 16; o; o >>= 1) var += __shfl_xor_sync(0xffffffffu, var, o);
        var *= (1.f/192.f);
        float rstd = rsqrtf(var + 1e-5f);
        #pragma unroll
        for (int u = 0; u < 6; ++u) {
            int ch = lane + u*32;
            As[row*196 + ch] = tf32f((v[u]-mean)*rstd*n2g[ch] + n2b[ch]);
        }
    }
    __syncthreads();

    float accC[2][6][4];
    #pragma unroll
    for (int i = 0; i < 2; ++i)
        #pragma unroll
        for (int j = 0; j < 6; ++j)
            #pragma unroll
            for (int r = 0; r < 4; ++r) accC[i][j][r] = 0.f;

    const int r1 = tid >> 2;
    const int q1 = (tid & 3) << 2;

    for (int hc = 0; hc < 12; ++hc) {
        float accH[2][2][4];
        #pragma unroll
        for (int i = 0; i < 2; ++i)
            #pragma unroll
            for (int j = 0; j < 2; ++j)
                #pragma unroll
                for (int r = 0; r < 4; ++r) accH[i][j][r] = 0.f;

        const float* W1p = w1 + (size_t)(hc*64 + r1) * CC + q1;
        float4 wreg = *(const float4*)(W1p);
        {
            float* d = Ws + 0*192*20 + r1*20 + q1;
            d[0] = tf32f(wreg.x); d[1] = tf32f(wreg.y);
            d[2] = tf32f(wreg.z); d[3] = tf32f(wreg.w);
        }
        __syncthreads();
        int buf = 0;
        for (int k0 = 0; ; k0 += 16) {
            const bool more = (k0 + 16) < CC;
            if (more) wreg = *(const float4*)(W1p + k0 + 16);
            #pragma unroll
            for (int ks = 0; ks < 16; ks += 8) {
                uint32_t afr[2][4];
                #pragma unroll
                for (int mt = 0; mt < 2; ++mt) {
                    int r = wm*32 + mt*16 + qrow;
                    int k = k0 + ks + qcol;
                    afr[mt][0] = __float_as_uint(As[r*196     + k]);
                    afr[mt][1] = __float_as_uint(As[(r+8)*196 + k]);
                    afr[mt][2] = __float_as_uint(As[r*196     + k + 4]);
                    afr[mt][3] = __float_as_uint(As[(r+8)*196 + k + 4]);
                }
                uint32_t bfr[2][2];
                #pragma unroll
                for (int nt = 0; nt < 2; ++nt) {
                    int n = wn*16 + nt*8 + qrow;
                    bfr[nt][0] = __float_as_uint(Ws[buf*192*20 + n*20 + ks + qcol]);
                    bfr[nt][1] = __float_as_uint(Ws[buf*192*20 + n*20 + ks + qcol + 4]);
                }
                #pragma unroll
                for (int mt = 0; mt < 2; ++mt)
                    #pragma unroll
                    for (int nt = 0; nt < 2; ++nt)
                        mma_tf32(accH[mt][nt], afr[mt], bfr[nt]);
            }
            if (!more) break;
            const int ob = buf ^ 1;
            float* d = Ws + ob*192*20 + r1*20 + q1;
            d[0] = tf32f(wreg.x); d[1] = tf32f(wreg.y);
            d[2] = tf32f(wreg.z); d[3] = tf32f(wreg.w);
            __syncthreads();
            buf = ob;
        }
        __syncthreads();

        #pragma unroll
        for (int mt = 0; mt < 2; ++mt) {
            #pragma unroll
            for (int nt = 0; nt < 2; ++nt) {
                #pragma unroll
                for (int half = 0; half < 2; ++half) {
                    int row = wm*32 + mt*16 + qrow + half*8;
                    #pragma unroll
                    for (int e = 0; e < 2; ++e) {
                        int col = wn*16 + nt*8 + qcol*2 + e;
                        float v = accH[mt][nt][half*2 + e] + b1[hc*64 + col];
                        v = 0.5f * v * (1.0f + erff(v * 0.70710678118654752f));
                        Hs[row*68 + col] = tf32f(v);
                    }
                }
            }
        }
        __syncthreads();

        float4 w2reg[3];
        #pragma unroll
        for (int i = 0; i < 3; ++i) {
            int idx = i*256 + tid;
            int r2 = idx >> 2, q2 = (idx & 3) << 2;
            w2reg[i] = *(const float4*)(w2 + (size_t)r2 * (4*CC) + hc*64 + q2);
        }
        #pragma unroll
        for (int i = 0; i < 3; ++i) {
            int idx = i*256 + tid;
            int r2 = idx >> 2, q2 = (idx & 3) << 2;
            float* d = Ws + 0*192*20 + r2*20 + q2;
            d[0] = tf32f(w2reg[i].x); d[1] = tf32f(w2reg[i].y);
            d[2] = tf32f(w2reg[i].z); d[3] = tf32f(w2reg[i].w);
        }
        __syncthreads();
        buf = 0;
        for (int k2 = 0; ; k2 += 16) {
            const bool more = (k2 + 16) < 64;
            if (more) {
                #pragma unroll
                for (int i = 0; i < 3; ++i) {
                    int idx = i*256 + tid;
                    int r2 = idx >> 2, q2 = (idx & 3) << 2;
                    w2reg[i] = *(const float4*)(w2 + (size_t)r2 * (4*CC) + hc*64 + k2 + 16 + q2);
                }
            }
            #pragma unroll
            for (int ks = 0; ks < 16; ks += 8) {
                uint32_t afr[2][4];
                #pragma unroll
                for (int mt = 0; mt < 2; ++mt) {
                    int r = wm*32 + mt*16 + qrow;
                    int k = k2 + ks + qcol;
                    afr[mt][0] = __float_as_uint(Hs[r*68     + k]);
                    afr[mt][1] = __float_as_uint(Hs[(r+8)*68 + k]);
                    afr[mt][2] = __float_as_uint(Hs[r*68     + k + 4]);
                    afr[mt][3] = __float_as_uint(Hs[(r+8)*68 + k + 4]);
                }
                uint32_t bfr[6][2];
                #pragma unroll
                for (int nt = 0; nt < 6; ++nt) {
                    int n = wn*48 + nt*8 + qrow;
                    bfr[nt][0] = __float_as_uint(Ws[buf*192*20 + n*20 + ks + qcol]);
                    bfr[nt][1] = __float_as_uint(Ws[buf*192*20 + n*20 + ks + qcol + 4]);
                }
                #pragma unroll
                for (int mt = 0; mt < 2; ++mt)
                    #pragma unroll
                    for (int nt = 0; nt < 6; ++nt)
                        mma_tf32(accC[mt][nt], afr[mt], bfr[nt]);
            }
            if (!more) break;
            const int ob = buf ^ 1;
            #pragma unroll
            for (int i = 0; i < 3; ++i) {
                int idx = i*256 + tid;
                int r2 = idx >> 2, q2 = (idx & 3) << 2;
                float* d = Ws + ob*192*20 + r2*20 + q2;
                d[0] = tf32f(w2reg[i].x); d[1] = tf32f(w2reg[i].y);
                d[2] = tf32f(w2reg[i].z); d[3] = tf32f(w2reg[i].w);
            }
            __syncthreads();
            buf = ob;
        }
        __syncthreads();
    }

    #pragma unroll
    for (int mt = 0; mt < 2; ++mt) {
        #pragma unroll
        for (int half = 0; half < 2; ++half) {
            int row = row0 + wm*32 + mt*16 + qrow + half*8;
            #pragma unroll
            for (int nt = 0; nt < 6; ++nt) {
                #pragma unroll
                for (int e = 0; e < 2; ++e) {
                    int col = wn*48 + nt*8 + qcol*2 + e;
                    float v = accC[mt][nt][half*2 + e] + b2[col]
                            + x1[(size_t)row * CC + col];
                    out[(size_t)row * CC + col] = v;
                }
            }
        }
    }
}

// ---------------- host launcher ----------------
extern "C" void kernel_launch(void* const* d_in, const int* in_sizes, int n_in,
                              void* d_out, int out_size)
{
    const float* x      = (const float*)d_in[0];
    const float* qkv_w  = (const float*)d_in[1];
    const float* qkv_b  = (const float*)d_in[2];
    const float* proj_w = (const float*)d_in[3];
    const float* proj_b = (const float*)d_in[4];
    const float* n1_g   = (const float*)d_in[5];
    const float* n1_b   = (const float*)d_in[6];
    const float* n2_g   = (const float*)d_in[7];
    const float* n2_b   = (const float*)d_in[8];
    const float* w1     = (const float*)d_in[9];
    const float* b1     = (const float*)d_in[10];
    const float* w2     = (const float*)d_in[11];
    const float* b2     = (const float*)d_in[12];
    float* out = (float*)d_out;

    float *hwin, *qkv, *attno, *x1;
    cudaGetSymbolAddress((void**)&hwin,  g_hwin);
    cudaGetSymbolAddress((void**)&qkv,   g_qkv);
    cudaGetSymbolAddress((void**)&attno, g_attno);
    cudaGetSymbolAddress((void**)&x1,    g_x1);

    const int FUSED_SMEM = (64*196 + 64*68 + 2*192*20) * 4;   // 98304 B
    cudaFuncSetAttribute(fused_mlp_k, cudaFuncAttributeMaxDynamicSharedMemorySize, FUSED_SMEM);

    // 1) LN1 + shift + window gather
    ln1_gather_k<<<NTOK/8, 256>>>(x, n1_g, n1_b, hwin);

    // 2) QKV GEMM
    mma_gemm_k<0><<<dim3((3*CC)/64, NTOK/128), 256>>>(hwin, qkv_w, qkv_b, nullptr, qkv,
                                                      NTOK, 3*CC, CC);

    // 3) tensor-core attention, one block per window
    attn_mma_k<<<NWIN, 256>>>(qkv, attno);

    // 4) proj GEMM + window reverse + residual -> x1 (token order)
    mma_gemm_k<3><<<dim3(CC/64, NTOK/128), 256>>>(attno, proj_w, proj_b, x, x1,
                                                  NTOK, CC, CC);

    // 5) fused LN2 + MLP1 + GELU + MLP2 + residual -> out
    fused_mlp_k<<<NTOK/64, 256, FUSED_SMEM>>>(x1, n2_g, n2_b, w1, b1, w2, b2, out);
}